// round 8
// baseline (speedup 1.0000x reference)
#include <cuda_runtime.h>
#include <cuda_fp16.h>
#include <cstdint>
#include <cstddef>

// Problem constants (fixed shapes for Hgnn_17394617548829)
#define N_NODESC 50000
#define N_HEDGESC 5000
#define NNZC 800000
#define IN_C 128
#define D1C 256
#define D2C 64

// Scan chunking: 256 elements per block
#define NBLK_H 20    // ceil(5000/256)
#define NBLK_N 196   // ceil(50000/256)
#define NBLK   216

// ---------------------------------------------------------------------------
// Scratch (static device globals; no allocation anywhere)
// ---------------------------------------------------------------------------
__device__ __half g_xh  [(size_t)N_NODESC * IN_C];   // 12.8 MB (x in fp16)
__device__ __half g_e1h [(size_t)N_HEDGESC * IN_C];  // 1.28 MB
__device__ __half g_a1h [(size_t)N_NODESC * IN_C];   // 12.8 MB (agg1 fp16)
__device__ __half g_hh  [(size_t)N_NODESC * D1C];    // 25.6 MB
__device__ __half g_y2h [(size_t)N_NODESC * D2C];    // 6.4 MB
__device__ __half g_e2h [(size_t)N_HEDGESC * D2C];   // 0.64 MB
__device__ __half g_w1h [(size_t)D1C * IN_C];        // W1^T [N=256][K=128]
__device__ __half g_w2h [(size_t)D2C * D1C];         // W2^T [N=64][K=256]
__device__ int   g_cnt [N_HEDGESC];
__device__ int   g_deg [N_NODESC];
__device__ int   g_hoff[N_HEDGESC + 1];
__device__ int   g_noff[N_NODESC + 1];
__device__ int   g_hcur[N_HEDGESC];
__device__ int   g_ncur[N_NODESC];
__device__ int   g_hlist[NNZC];
__device__ int   g_nlist[NNZC];
__device__ float g_dinv[N_NODESC];
__device__ float g_binv[N_HEDGESC];
__device__ int   g_part[NBLK];
__device__ int   g_partoff[NBLK];
__device__ int   g_bar0;            // grid-barrier counters (reset in cvt_k)
__device__ int   g_bar1;

// ---------------------------------------------------------------------------
// fp16 helpers
// ---------------------------------------------------------------------------
__device__ __forceinline__ void acc_h8(float4& a, float4& b, uint4 u) {
    float2 f0 = __half22float2(*reinterpret_cast<__half2*>(&u.x));
    float2 f1 = __half22float2(*reinterpret_cast<__half2*>(&u.y));
    float2 f2 = __half22float2(*reinterpret_cast<__half2*>(&u.z));
    float2 f3 = __half22float2(*reinterpret_cast<__half2*>(&u.w));
    a.x += f0.x; a.y += f0.y; a.z += f1.x; a.w += f1.y;
    b.x += f2.x; b.y += f2.y; b.z += f3.x; b.w += f3.y;
}

__device__ __forceinline__ uint4 pack_h8(float4 a, float4 b) {
    __half2 h0 = __floats2half2_rn(a.x, a.y);
    __half2 h1 = __floats2half2_rn(a.z, a.w);
    __half2 h2 = __floats2half2_rn(b.x, b.y);
    __half2 h3 = __floats2half2_rn(b.z, b.w);
    uint4 u;
    u.x = *reinterpret_cast<unsigned*>(&h0);
    u.y = *reinterpret_cast<unsigned*>(&h1);
    u.z = *reinterpret_cast<unsigned*>(&h2);
    u.w = *reinterpret_cast<unsigned*>(&h3);
    return u;
}

__device__ __forceinline__ uint2 pack_h4(float x, float y, float z, float w) {
    __half2 h0 = __floats2half2_rn(x, y);
    __half2 h1 = __floats2half2_rn(z, w);
    uint2 u;
    u.x = *reinterpret_cast<unsigned*>(&h0);
    u.y = *reinterpret_cast<unsigned*>(&h1);
    return u;
}

// ---------------------------------------------------------------------------
// 0. conversions + zero counters + reset grid-barrier
// ---------------------------------------------------------------------------
__global__ void __launch_bounds__(256) cvt_k(const float* __restrict__ x,
                                             const float* __restrict__ W1,
                                             const float* __restrict__ W2) {
    int i = blockIdx.x * blockDim.x + threadIdx.x;
    int stride = gridDim.x * blockDim.x;
    if (i == 0) { g_bar0 = 0; g_bar1 = 0; }
    const float4* x4 = reinterpret_cast<const float4*>(x);
    uint2* xh2 = reinterpret_cast<uint2*>(g_xh);
    for (int j = i; j < N_NODESC * IN_C / 4; j += stride) {
        float4 v = x4[j];
        xh2[j] = pack_h4(v.x, v.y, v.z, v.w);
    }
    for (int j = i; j < D1C * IN_C; j += stride) {
        int n = j / IN_C, k = j % IN_C;
        g_w1h[j] = __float2half(W1[(size_t)k * D1C + n]);
    }
    for (int j = i; j < D2C * D1C; j += stride) {
        int n = j / D1C, k = j % D1C;
        g_w2h[j] = __float2half(W2[(size_t)k * D2C + n]);
    }
    for (int j = i; j < N_NODESC; j += stride) g_deg[j] = 0;
    for (int j = i; j < N_HEDGESC; j += stride) g_cnt[j] = 0;
}

// ---------------------------------------------------------------------------
// 1. degree histograms (4 edges per thread, independent chains)
// ---------------------------------------------------------------------------
__global__ void __launch_bounds__(256) hist_k(const int* __restrict__ ni,
                                              const int* __restrict__ hi) {
    int i = blockIdx.x * blockDim.x + threadIdx.x;
    if (4 * i >= NNZC) return;
    int4 nn = *reinterpret_cast<const int4*>(ni + 4 * i);
    int4 hh = *reinterpret_cast<const int4*>(hi + 4 * i);
    atomicAdd(&g_deg[nn.x], 1);
    atomicAdd(&g_deg[nn.y], 1);
    atomicAdd(&g_deg[nn.z], 1);
    atomicAdd(&g_deg[nn.w], 1);
    atomicAdd(&g_cnt[hh.x], 1);
    atomicAdd(&g_cnt[hh.y], 1);
    atomicAdd(&g_cnt[hh.z], 1);
    atomicAdd(&g_cnt[hh.w], 1);
}

// ---------------------------------------------------------------------------
// 2. fused segmented exclusive scan: psum + chunk-scan + fill in ONE kernel.
//    216 blocks, all co-resident (148 SMs, 8 warps/block) -> software grid
//    barrier via g_bar0/g_bar1 (reset by cvt_k) cannot deadlock.
// ---------------------------------------------------------------------------
__global__ void __launch_bounds__(256) scan_k() {
    __shared__ int sh[256];
    const int b   = blockIdx.x;
    const int tid = threadIdx.x;
    const int* src; int* off; int* cur; float* inv;
    int idx, n;
    if (b < NBLK_H) {
        src = g_cnt; off = g_hoff; cur = g_hcur; inv = g_binv;
        idx = b * 256 + tid; n = N_HEDGESC;
    } else {
        src = g_deg; off = g_noff; cur = g_ncur; inv = g_dinv;
        idx = (b - NBLK_H) * 256 + tid; n = N_NODESC;
    }
    int v = (idx < n) ? src[idx] : 0;

    // --- phase 1: block-local inclusive scan (also yields block total) ---
    sh[tid] = v;
    __syncthreads();
    for (int d = 1; d < 256; d <<= 1) {
        int t = (tid >= d) ? sh[tid - d] : 0;
        __syncthreads();
        sh[tid] += t;
        __syncthreads();
    }
    int incl = sh[tid];
    if (tid == 255) g_part[b] = incl;   // block total
    __threadfence();
    __syncthreads();
    if (tid == 0) atomicAdd(&g_bar0, 1);

    // --- phase 2: block 0 scans the 216 partials ---
    if (b == 0) {
        if (tid == 0) {
            while (atomicAdd(&g_bar0, 0) < NBLK) __nanosleep(64);
            __threadfence();
            int run = 0;
            for (int i = 0; i < NBLK_H; i++) { int c = g_part[i]; g_partoff[i] = run; run += c; }
            run = 0;
            for (int i = NBLK_H; i < NBLK; i++) { int c = g_part[i]; g_partoff[i] = run; run += c; }
            __threadfence();
            atomicExch(&g_bar1, 1);
        }
    }
    if (tid == 0) {
        while (atomicAdd(&g_bar1, 0) == 0) __nanosleep(64);
    }
    __syncthreads();
    __threadfence();

    // --- phase 3: fill offsets / cursors / inverse degrees ---
    if (idx < n) {
        int excl = incl - v + g_partoff[b];
        off[idx] = excl;
        cur[idx] = excl;
        inv[idx] = (v > 0) ? 1.0f / (float)v : 0.0f;
    }
    if (b == 0 && tid == 0) {
        g_hoff[N_HEDGESC] = NNZC;
        g_noff[N_NODESC]  = NNZC;
    }
}

// ---------------------------------------------------------------------------
// 3. scatter edges into both CSR member lists (4 edges per thread)
// ---------------------------------------------------------------------------
__global__ void __launch_bounds__(256) build_k(const int* __restrict__ ni,
                                               const int* __restrict__ hi) {
    int i = blockIdx.x * blockDim.x + threadIdx.x;
    if (4 * i >= NNZC) return;
    int4 nn = *reinterpret_cast<const int4*>(ni + 4 * i);
    int4 hh = *reinterpret_cast<const int4*>(hi + 4 * i);
    int p0 = atomicAdd(&g_hcur[hh.x], 1);
    int p1 = atomicAdd(&g_hcur[hh.y], 1);
    int p2 = atomicAdd(&g_hcur[hh.z], 1);
    int p3 = atomicAdd(&g_hcur[hh.w], 1);
    int q0 = atomicAdd(&g_ncur[nn.x], 1);
    int q1 = atomicAdd(&g_ncur[nn.y], 1);
    int q2 = atomicAdd(&g_ncur[nn.z], 1);
    int q3 = atomicAdd(&g_ncur[nn.w], 1);
    g_hlist[p0] = nn.x;
    g_hlist[p1] = nn.y;
    g_hlist[p2] = nn.z;
    g_hlist[p3] = nn.w;
    g_nlist[q0] = hh.x;
    g_nlist[q1] = hh.y;
    g_nlist[q2] = hh.z;
    g_nlist[q3] = hh.w;
}

// ---------------------------------------------------------------------------
// Gather kernels, fp16 payloads, fp32 accumulation, LDG.128.
// 128 ch: 16-lane group per segment (16 x uint4 = 128 halves).
// 64 ch:   8-lane group per segment ( 8 x uint4 =  64 halves).
// ---------------------------------------------------------------------------
// e1h[h] = binv[h] * sum x_h[n]
__global__ void __launch_bounds__(256) n2h1_k() {
    int g = blockIdx.x * 16 + (threadIdx.x >> 4);
    if (g >= N_HEDGESC) return;
    int lane = threadIdx.x & 15;
    int base = g_hoff[g], end = g_hoff[g + 1];
    float4 p0 = make_float4(0.f, 0.f, 0.f, 0.f), p1 = p0, q0 = p0, q1 = p0;
    int j = base;
    for (; j + 4 <= end; j += 4) {
        int n0 = __ldg(g_hlist + j + 0);
        int n1 = __ldg(g_hlist + j + 1);
        int n2 = __ldg(g_hlist + j + 2);
        int n3 = __ldg(g_hlist + j + 3);
        uint4 u0 = __ldg(reinterpret_cast<const uint4*>(g_xh + (size_t)n0 * IN_C) + lane);
        uint4 u1 = __ldg(reinterpret_cast<const uint4*>(g_xh + (size_t)n1 * IN_C) + lane);
        uint4 u2 = __ldg(reinterpret_cast<const uint4*>(g_xh + (size_t)n2 * IN_C) + lane);
        uint4 u3 = __ldg(reinterpret_cast<const uint4*>(g_xh + (size_t)n3 * IN_C) + lane);
        acc_h8(p0, p1, u0); acc_h8(q0, q1, u1); acc_h8(p0, p1, u2); acc_h8(q0, q1, u3);
    }
    for (; j < end; j++) {
        int n0 = __ldg(g_hlist + j);
        uint4 u0 = __ldg(reinterpret_cast<const uint4*>(g_xh + (size_t)n0 * IN_C) + lane);
        acc_h8(p0, p1, u0);
    }
    float bi = g_binv[g];
    float4 r0, r1;
    r0.x = (p0.x + q0.x) * bi; r0.y = (p0.y + q0.y) * bi;
    r0.z = (p0.z + q0.z) * bi; r0.w = (p0.w + q0.w) * bi;
    r1.x = (p1.x + q1.x) * bi; r1.y = (p1.y + q1.y) * bi;
    r1.z = (p1.z + q1.z) * bi; r1.w = (p1.w + q1.w) * bi;
    reinterpret_cast<uint4*>(g_e1h + (size_t)g * IN_C)[lane] = pack_h8(r0, r1);
}

// a1h[n] = dinv[n] * sum e1h[h]
__global__ void __launch_bounds__(256) h2n1_k() {
    int g = blockIdx.x * 16 + (threadIdx.x >> 4);
    if (g >= N_NODESC) return;
    int lane = threadIdx.x & 15;
    int base = g_noff[g], end = g_noff[g + 1];
    float4 p0 = make_float4(0.f, 0.f, 0.f, 0.f), p1 = p0, q0 = p0, q1 = p0;
    int j = base;
    for (; j + 4 <= end; j += 4) {
        int h0 = __ldg(g_nlist + j + 0);
        int h1 = __ldg(g_nlist + j + 1);
        int h2 = __ldg(g_nlist + j + 2);
        int h3 = __ldg(g_nlist + j + 3);
        uint4 u0 = __ldg(reinterpret_cast<const uint4*>(g_e1h + (size_t)h0 * IN_C) + lane);
        uint4 u1 = __ldg(reinterpret_cast<const uint4*>(g_e1h + (size_t)h1 * IN_C) + lane);
        uint4 u2 = __ldg(reinterpret_cast<const uint4*>(g_e1h + (size_t)h2 * IN_C) + lane);
        uint4 u3 = __ldg(reinterpret_cast<const uint4*>(g_e1h + (size_t)h3 * IN_C) + lane);
        acc_h8(p0, p1, u0); acc_h8(q0, q1, u1); acc_h8(p0, p1, u2); acc_h8(q0, q1, u3);
    }
    for (; j < end; j++) {
        int h0 = __ldg(g_nlist + j);
        uint4 u0 = __ldg(reinterpret_cast<const uint4*>(g_e1h + (size_t)h0 * IN_C) + lane);
        acc_h8(p0, p1, u0);
    }
    float di = g_dinv[g];
    float4 r0, r1;
    r0.x = (p0.x + q0.x) * di; r0.y = (p0.y + q0.y) * di;
    r0.z = (p0.z + q0.z) * di; r0.w = (p0.w + q0.w) * di;
    r1.x = (p1.x + q1.x) * di; r1.y = (p1.y + q1.y) * di;
    r1.z = (p1.z + q1.z) * di; r1.w = (p1.w + q1.w) * di;
    reinterpret_cast<uint4*>(g_a1h + (size_t)g * IN_C)[lane] = pack_h8(r0, r1);
}

// e2h[h] = binv[h] * sum y2h[n]   (64 ch, 8-lane groups)
__global__ void __launch_bounds__(256) n2h2_k() {
    int g = blockIdx.x * 32 + (threadIdx.x >> 3);
    if (g >= N_HEDGESC) return;
    int lane = threadIdx.x & 7;
    int base = g_hoff[g], end = g_hoff[g + 1];
    float4 p0 = make_float4(0.f, 0.f, 0.f, 0.f), p1 = p0, q0 = p0, q1 = p0;
    int j = base;
    for (; j + 4 <= end; j += 4) {
        int n0 = __ldg(g_hlist + j + 0);
        int n1 = __ldg(g_hlist + j + 1);
        int n2 = __ldg(g_hlist + j + 2);
        int n3 = __ldg(g_hlist + j + 3);
        uint4 u0 = __ldg(reinterpret_cast<const uint4*>(g_y2h + (size_t)n0 * D2C) + lane);
        uint4 u1 = __ldg(reinterpret_cast<const uint4*>(g_y2h + (size_t)n1 * D2C) + lane);
        uint4 u2 = __ldg(reinterpret_cast<const uint4*>(g_y2h + (size_t)n2 * D2C) + lane);
        uint4 u3 = __ldg(reinterpret_cast<const uint4*>(g_y2h + (size_t)n3 * D2C) + lane);
        acc_h8(p0, p1, u0); acc_h8(q0, q1, u1); acc_h8(p0, p1, u2); acc_h8(q0, q1, u3);
    }
    for (; j < end; j++) {
        int n0 = __ldg(g_hlist + j);
        uint4 u0 = __ldg(reinterpret_cast<const uint4*>(g_y2h + (size_t)n0 * D2C) + lane);
        acc_h8(p0, p1, u0);
    }
    float bi = g_binv[g];
    float4 r0, r1;
    r0.x = (p0.x + q0.x) * bi; r0.y = (p0.y + q0.y) * bi;
    r0.z = (p0.z + q0.z) * bi; r0.w = (p0.w + q0.w) * bi;
    r1.x = (p1.x + q1.x) * bi; r1.y = (p1.y + q1.y) * bi;
    r1.z = (p1.z + q1.z) * bi; r1.w = (p1.w + q1.w) * bi;
    reinterpret_cast<uint4*>(g_e2h + (size_t)g * D2C)[lane] = pack_h8(r0, r1);
}

// out[n] = relu(dinv[n] * sum e2h[h] + b2)   (fp32 out, 8-lane groups -> 8 floats)
__global__ void __launch_bounds__(256) h2n2_k(const float* __restrict__ b2,
                                              float* __restrict__ out) {
    int g = blockIdx.x * 32 + (threadIdx.x >> 3);
    if (g >= N_NODESC) return;
    int lane = threadIdx.x & 7;
    int base = g_noff[g], end = g_noff[g + 1];
    float4 p0 = make_float4(0.f, 0.f, 0.f, 0.f), p1 = p0, q0 = p0, q1 = p0;
    int j = base;
    for (; j + 4 <= end; j += 4) {
        int h0 = __ldg(g_nlist + j + 0);
        int h1 = __ldg(g_nlist + j + 1);
        int h2 = __ldg(g_nlist + j + 2);
        int h3 = __ldg(g_nlist + j + 3);
        uint4 u0 = __ldg(reinterpret_cast<const uint4*>(g_e2h + (size_t)h0 * D2C) + lane);
        uint4 u1 = __ldg(reinterpret_cast<const uint4*>(g_e2h + (size_t)h1 * D2C) + lane);
        uint4 u2 = __ldg(reinterpret_cast<const uint4*>(g_e2h + (size_t)h2 * D2C) + lane);
        uint4 u3 = __ldg(reinterpret_cast<const uint4*>(g_e2h + (size_t)h3 * D2C) + lane);
        acc_h8(p0, p1, u0); acc_h8(q0, q1, u1); acc_h8(p0, p1, u2); acc_h8(q0, q1, u3);
    }
    for (; j < end; j++) {
        int h0 = __ldg(g_nlist + j);
        uint4 u0 = __ldg(reinterpret_cast<const uint4*>(g_e2h + (size_t)h0 * D2C) + lane);
        acc_h8(p0, p1, u0);
    }
    float di = g_dinv[g];
    float4 ba = __ldg(reinterpret_cast<const float4*>(b2) + 2 * lane);
    float4 bb = __ldg(reinterpret_cast<const float4*>(b2) + 2 * lane + 1);
    float4 r0, r1;
    r0.x = fmaxf(fmaf(p0.x + q0.x, di, ba.x), 0.f);
    r0.y = fmaxf(fmaf(p0.y + q0.y, di, ba.y), 0.f);
    r0.z = fmaxf(fmaf(p0.z + q0.z, di, ba.z), 0.f);
    r0.w = fmaxf(fmaf(p0.w + q0.w, di, ba.w), 0.f);
    r1.x = fmaxf(fmaf(p1.x + q1.x, di, bb.x), 0.f);
    r1.y = fmaxf(fmaf(p1.y + q1.y, di, bb.y), 0.f);
    r1.z = fmaxf(fmaf(p1.z + q1.z, di, bb.z), 0.f);
    r1.w = fmaxf(fmaf(p1.w + q1.w, di, bb.w), 0.f);
    reinterpret_cast<float4*>(out + (size_t)g * D2C)[2 * lane]     = r0;
    reinterpret_cast<float4*>(out + (size_t)g * D2C)[2 * lane + 1] = r1;
}

// ---------------------------------------------------------------------------
// fp16 tensor-core GEMM (unchanged from R6 — verified correct).
// ---------------------------------------------------------------------------
__device__ __forceinline__ void mma_f16(float& d0, float& d1, float& d2, float& d3,
                                        uint32_t a0, uint32_t a1, uint32_t a2, uint32_t a3,
                                        uint32_t b0, uint32_t b1) {
    asm volatile(
        "mma.sync.aligned.m16n8k16.row.col.f32.f16.f16.f32 "
        "{%0,%1,%2,%3}, {%4,%5,%6,%7}, {%8,%9}, {%0,%1,%2,%3};"
        : "+f"(d0), "+f"(d1), "+f"(d2), "+f"(d3)
        : "r"(a0), "r"(a1), "r"(a2), "r"(a3), "r"(b0), "r"(b1));
}

template <int BM, int BN, int BK, int WARPS_M, int WARPS_N, bool EPI>
__device__ __forceinline__ void gemm_f16_body(const __half* __restrict__ A,
                                              const __half* __restrict__ Bt,
                                              const float* __restrict__ bias,
                                              __half* __restrict__ C,
                                              int M, int N, int K) {
    constexpr int THREADS = WARPS_M * WARPS_N * 32;
    constexpr int WM = BM / WARPS_M;
    constexpr int WN = BN / WARPS_N;
    constexpr int MI = WM / 16;
    constexpr int NI = WN / 8;
    constexpr int PAD = 8;
    constexpr int AV = (BM * BK / 8) / THREADS;
    constexpr int BV = (BN * BK / 8) / THREADS;

    __shared__ __align__(16) __half As[BM][BK + PAD];
    __shared__ __align__(16) __half Bs[BN][BK + PAD];

    const int tid  = threadIdx.x;
    const int warp = tid >> 5;
    const int lane = tid & 31;
    const int wm   = warp / WARPS_N;
    const int wn   = warp % WARPS_N;
    const int row0 = blockIdx.y * BM;
    const int col0 = blockIdx.x * BN;
    const int lq   = lane >> 2;
    const int lr   = lane & 3;

    float acc[MI][NI][4];
#pragma unroll
    for (int i = 0; i < MI; i++)
#pragma unroll
        for (int j = 0; j < NI; j++)
#pragma unroll
            for (int c = 0; c < 4; c++) acc[i][j][c] = 0.f;

    for (int kt = 0; kt < K; kt += BK) {
#pragma unroll
        for (int i = 0; i < AV; i++) {
            int idx = tid + i * THREADS;
            int m   = idx / (BK / 8);
            int kc  = (idx % (BK / 8)) * 8;
            int grow = row0 + m;
            uint4 v = make_uint4(0, 0, 0, 0);
            if (grow < M)
                v = __ldg(reinterpret_cast<const uint4*>(A + (size_t)grow * K + kt + kc));
            *reinterpret_cast<uint4*>(&As[m][kc]) = v;
        }
#pragma unroll
        for (int i = 0; i < BV; i++) {
            int idx = tid + i * THREADS;
            int n   = idx / (BK / 8);
            int kc  = (idx % (BK / 8)) * 8;
            uint4 v = __ldg(reinterpret_cast<const uint4*>(Bt + (size_t)(col0 + n) * K + kt + kc));
            *reinterpret_cast<uint4*>(&Bs[n][kc]) = v;
        }
        __syncthreads();

#pragma unroll
        for (int ks = 0; ks < BK; ks += 16) {
            uint32_t af[MI][4];
            uint32_t bf[NI][2];
#pragma unroll
            for (int i = 0; i < MI; i++) {
                int m0 = wm * WM + i * 16;
                af[i][0] = *reinterpret_cast<const uint32_t*>(&As[m0 + lq    ][ks + 2 * lr    ]);
                af[i][1] = *reinterpret_cast<const uint32_t*>(&As[m0 + lq + 8][ks + 2 * lr    ]);
                af[i][2] = *reinterpret_cast<const uint32_t*>(&As[m0 + lq    ][ks + 2 * lr + 8]);
                af[i][3] = *reinterpret_cast<const uint32_t*>(&As[m0 + lq + 8][ks + 2 * lr + 8]);
            }
#pragma unroll
            for (int j = 0; j < NI; j++) {
                int n0 = wn * WN + j * 8;
                bf[j][0] = *reinterpret_cast<const uint32_t*>(&Bs[n0 + lq][ks + 2 * lr    ]);
                bf[j][1] = *reinterpret_cast<const uint32_t*>(&Bs[n0 + lq][ks + 2 * lr + 8]);
            }
#pragma unroll
            for (int i = 0; i < MI; i++)
#pragma unroll
                for (int j = 0; j < NI; j++)
                    mma_f16(acc[i][j][0], acc[i][j][1], acc[i][j][2], acc[i][j][3],
                            af[i][0], af[i][1], af[i][2], af[i][3],
                            bf[j][0], bf[j][1]);
        }
        __syncthreads();
    }

#pragma unroll
    for (int i = 0; i < MI; i++) {
#pragma unroll
        for (int j = 0; j < NI; j++) {
            int row = row0 + wm * WM + i * 16 + lq;
            int col = col0 + wn * WN + j * 8 + 2 * lr;
            float2 v0 = make_float2(acc[i][j][0], acc[i][j][1]);
            float2 v1 = make_float2(acc[i][j][2], acc[i][j][3]);
            if (EPI) {
                float b0 = bias[col], b1 = bias[col + 1];
                v0.x = fmaxf(v0.x + b0, 0.f);
                v0.y = fmaxf(v0.y + b1, 0.f);
                v1.x = fmaxf(v1.x + b0, 0.f);
                v1.y = fmaxf(v1.y + b1, 0.f);
            }
            if (row < M)
                *reinterpret_cast<__half2*>(&C[(size_t)row * N + col]) =
                    __floats2half2_rn(v0.x, v0.y);
            if (row + 8 < M)
                *reinterpret_cast<__half2*>(&C[(size_t)(row + 8) * N + col]) =
                    __floats2half2_rn(v1.x, v1.y);
        }
    }
}

// GEMM1: g_hh = relu(g_a1h @ W1 + b1)   [50000x128]@[128x256]
__global__ void __launch_bounds__(256) gemm1_k(const float* __restrict__ b1) {
    gemm_f16_body<128, 128, 32, 2, 4, true>(g_a1h, g_w1h, b1, g_hh, N_NODESC, D1C, IN_C);
}

// GEMM2: g_y2h = g_hh @ W2   [50000x256]@[256x64]
__global__ void __launch_bounds__(256) gemm2_k() {
    gemm_f16_body<128, 64, 32, 4, 2, false>(g_hh, g_w2h, nullptr, g_y2h, N_NODESC, D2C, D1C);
}

// ---------------------------------------------------------------------------
// Launch (10 kernels)
// ---------------------------------------------------------------------------
extern "C" void kernel_launch(void* const* d_in, const int* in_sizes, int n_in,
                              void* d_out, int out_size) {
    const float* x    = (const float*)d_in[0];
    const int*   edge = (const int*)d_in[1];
    const float* W1   = (const float*)d_in[2];
    const float* b1   = (const float*)d_in[3];
    const float* W2   = (const float*)d_in[4];
    const float* b2   = (const float*)d_in[5];
    float*       out  = (float*)d_out;

    const int* ni = edge;          // edge[0] = node_idx
    const int* hi = edge + NNZC;   // edge[1] = hedge_idx

    // conversions + zero + barrier reset; CSR construction
    cvt_k<<<1024, 256>>>(x, W1, W2);
    hist_k<<<(NNZC / 4 + 255) / 256, 256>>>(ni, hi);
    scan_k<<<NBLK, 256>>>();
    build_k<<<(NNZC / 4 + 255) / 256, 256>>>(ni, hi);

    // Layer 1 aggregation at 128 channels (fp16 gather)
    n2h1_k<<<(N_HEDGESC + 15) / 16, 256>>>();
    h2n1_k<<<(N_NODESC + 15) / 16, 256>>>();

    // h = relu(agg1 @ W1 + b1) ; y2 = h @ W2   (fp16 tensor cores)
    {
        dim3 g1(D1C / 128, (N_NODESC + 127) / 128);
        gemm1_k<<<g1, 256>>>(b1);
        dim3 g2(D2C / 64, (N_NODESC + 127) / 128);
        gemm2_k<<<g2, 256>>>();
    }

    // Layer 2 aggregation at 64 channels (fp16 gather) + fused final epilogue
    n2h2_k<<<(N_HEDGESC + 31) / 32, 256>>>();
    h2n2_k<<<(N_NODESC + 31) / 32, 256>>>(b2, out);
}

// round 9
// speedup vs baseline: 1.4348x; 1.4348x over previous
#include <cuda_runtime.h>
#include <cuda_fp16.h>
#include <cstdint>
#include <cstddef>

// Problem constants (fixed shapes for Hgnn_17394617548829)
#define N_NODESC 50000
#define N_HEDGESC 5000
#define NNZC 800000
#define IN_C 128
#define D1C 256
#define D2C 64

// Scan chunking: 256 elements per block
#define NBLK_H 20    // ceil(5000/256)
#define NBLK_N 196   // ceil(50000/256)
#define NBLK   216

// ---------------------------------------------------------------------------
// Scratch (static device globals; no allocation anywhere)
// ---------------------------------------------------------------------------
__device__ __half g_xh  [(size_t)N_NODESC * IN_C];   // 12.8 MB (x in fp16)
__device__ __half g_e1h [(size_t)N_HEDGESC * IN_C];  // 1.28 MB
__device__ __half g_a1h [(size_t)N_NODESC * IN_C];   // 12.8 MB (agg1 fp16)
__device__ __half g_hh  [(size_t)N_NODESC * D1C];    // 25.6 MB
__device__ __half g_y2h [(size_t)N_NODESC * D2C];    // 6.4 MB
__device__ __half g_e2h [(size_t)N_HEDGESC * D2C];   // 0.64 MB
__device__ __half g_w1h [(size_t)D1C * IN_C];        // W1^T [N=256][K=128]
__device__ __half g_w2h [(size_t)D2C * D1C];         // W2^T [N=64][K=256]
__device__ int   g_cnt [N_HEDGESC];
__device__ int   g_deg [N_NODESC];
__device__ int   g_hoff[N_HEDGESC + 1];
__device__ int   g_noff[N_NODESC + 1];
__device__ int   g_hcur[N_HEDGESC];
__device__ int   g_ncur[N_NODESC];
__device__ int   g_hlist[NNZC];
__device__ int   g_nlist[NNZC];
__device__ float g_dinv[N_NODESC];
__device__ float g_binv[N_HEDGESC];
__device__ int   g_part[NBLK];
__device__ int   g_partoff[NBLK];
__device__ int   g_bar0;            // grid-barrier counters (reset in cvt_k)
__device__ int   g_bar1;

// ---------------------------------------------------------------------------
// fp16 helpers
// ---------------------------------------------------------------------------
__device__ __forceinline__ void acc_h2(float4& a, uint2 u) {
    __half2 p0 = *reinterpret_cast<__half2*>(&u.x);
    __half2 p1 = *reinterpret_cast<__half2*>(&u.y);
    float2 f0 = __half22float2(p0);
    float2 f1 = __half22float2(p1);
    a.x += f0.x; a.y += f0.y; a.z += f1.x; a.w += f1.y;
}

__device__ __forceinline__ uint2 pack_h2(float x, float y, float z, float w) {
    __half2 h0 = __floats2half2_rn(x, y);
    __half2 h1 = __floats2half2_rn(z, w);
    uint2 u;
    u.x = *reinterpret_cast<unsigned*>(&h0);
    u.y = *reinterpret_cast<unsigned*>(&h1);
    return u;
}

// ---------------------------------------------------------------------------
// 0. conversions + zero counters + grid-barrier reset (fused)
// ---------------------------------------------------------------------------
__global__ void __launch_bounds__(256) cvt_k(const float* __restrict__ x,
                                             const float* __restrict__ W1,
                                             const float* __restrict__ W2) {
    int i = blockIdx.x * blockDim.x + threadIdx.x;
    int stride = gridDim.x * blockDim.x;
    if (i == 0) { g_bar0 = 0; g_bar1 = 0; }
    const float4* x4 = reinterpret_cast<const float4*>(x);
    uint2* xh2 = reinterpret_cast<uint2*>(g_xh);
    for (int j = i; j < N_NODESC * IN_C / 4; j += stride) {
        float4 v = x4[j];
        xh2[j] = pack_h2(v.x, v.y, v.z, v.w);
    }
    for (int j = i; j < D1C * IN_C; j += stride) {
        int n = j / IN_C, k = j % IN_C;
        g_w1h[j] = __float2half(W1[(size_t)k * D1C + n]);
    }
    for (int j = i; j < D2C * D1C; j += stride) {
        int n = j / D1C, k = j % D1C;
        g_w2h[j] = __float2half(W2[(size_t)k * D2C + n]);
    }
    for (int j = i; j < N_NODESC; j += stride) g_deg[j] = 0;
    for (int j = i; j < N_HEDGESC; j += stride) g_cnt[j] = 0;
}

// ---------------------------------------------------------------------------
// 1. degree histograms (2 edges per thread — R6 proven config)
// ---------------------------------------------------------------------------
__global__ void __launch_bounds__(256) hist_k(const int* __restrict__ ni,
                                              const int* __restrict__ hi) {
    int i = blockIdx.x * blockDim.x + threadIdx.x;
    if (2 * i >= NNZC) return;
    int2 nn = *reinterpret_cast<const int2*>(ni + 2 * i);
    int2 hh = *reinterpret_cast<const int2*>(hi + 2 * i);
    atomicAdd(&g_deg[nn.x], 1);
    atomicAdd(&g_deg[nn.y], 1);
    atomicAdd(&g_cnt[hh.x], 1);
    atomicAdd(&g_cnt[hh.y], 1);
}

// ---------------------------------------------------------------------------
// 2. fused segmented exclusive scan (one kernel, grid barrier).
//    Phase 2 (216-partial scan) runs in BLOCK 0 SHARED MEMORY — the R7
//    regression was doing this loop through global/L2.
//    216 blocks <= 1 wave (148 SMs, small footprint) -> no deadlock.
// ---------------------------------------------------------------------------
__global__ void __launch_bounds__(256) scan_k() {
    __shared__ int sh[256];
    __shared__ int shp[NBLK];
    const int b   = blockIdx.x;
    const int tid = threadIdx.x;
    const int* src; int* off; int* cur; float* inv;
    int idx, n;
    if (b < NBLK_H) {
        src = g_cnt; off = g_hoff; cur = g_hcur; inv = g_binv;
        idx = b * 256 + tid; n = N_HEDGESC;
    } else {
        src = g_deg; off = g_noff; cur = g_ncur; inv = g_dinv;
        idx = (b - NBLK_H) * 256 + tid; n = N_NODESC;
    }
    int v = (idx < n) ? src[idx] : 0;

    // --- phase 1: block-local inclusive scan + publish block total ---
    sh[tid] = v;
    __syncthreads();
    for (int d = 1; d < 256; d <<= 1) {
        int t = (tid >= d) ? sh[tid - d] : 0;
        __syncthreads();
        sh[tid] += t;
        __syncthreads();
    }
    int incl = sh[tid];
    if (tid == 255) {
        g_part[b] = incl;
        __threadfence();
        atomicAdd(&g_bar0, 1);
    }

    // --- phase 2: block 0 scans the 216 partials IN SHARED MEMORY ---
    if (b == 0) {
        if (tid == 0) {
            while (atomicAdd(&g_bar0, 0) < NBLK) __nanosleep(32);
        }
        __syncthreads();
        __threadfence();           // acquire: make g_part[] visible
        if (tid < NBLK) shp[tid] = g_part[tid];
        __syncthreads();
        if (tid == 0) {
            int run = 0;
            for (int i = 0; i < NBLK_H; i++) { int c = shp[i]; shp[i] = run; run += c; }
            run = 0;
            for (int i = NBLK_H; i < NBLK; i++) { int c = shp[i]; shp[i] = run; run += c; }
        }
        __syncthreads();
        if (tid < NBLK) g_partoff[tid] = shp[tid];
        __threadfence();
        __syncthreads();
        if (tid == 0) atomicExch(&g_bar1, 1);
    }
    if (tid == 0) {
        while (atomicAdd(&g_bar1, 0) == 0) __nanosleep(32);
    }
    __syncthreads();
    __threadfence();               // acquire: make g_partoff[] visible

    // --- phase 3: fill offsets / cursors / inverse degrees ---
    if (idx < n) {
        int excl = incl - v + g_partoff[b];
        off[idx] = excl;
        cur[idx] = excl;
        inv[idx] = (v > 0) ? 1.0f / (float)v : 0.0f;
    }
    if (b == 0 && tid == 0) {
        g_hoff[N_HEDGESC] = NNZC;
        g_noff[N_NODESC]  = NNZC;
    }
}

// ---------------------------------------------------------------------------
// 3. scatter edges into both CSR member lists (2 edges per thread — R6 proven)
// ---------------------------------------------------------------------------
__global__ void __launch_bounds__(256) build_k(const int* __restrict__ ni,
                                               const int* __restrict__ hi) {
    int i = blockIdx.x * blockDim.x + threadIdx.x;
    if (2 * i >= NNZC) return;
    int2 nn = *reinterpret_cast<const int2*>(ni + 2 * i);
    int2 hh = *reinterpret_cast<const int2*>(hi + 2 * i);
    int p0 = atomicAdd(&g_hcur[hh.x], 1);
    int p1 = atomicAdd(&g_hcur[hh.y], 1);
    int q0 = atomicAdd(&g_ncur[nn.x], 1);
    int q1 = atomicAdd(&g_ncur[nn.y], 1);
    g_hlist[p0] = nn.x;
    g_hlist[p1] = nn.y;
    g_nlist[q0] = hh.x;
    g_nlist[q1] = hh.y;
}

// ---------------------------------------------------------------------------
// Gather kernels — exact R6 proven versions (fp16 payload, fp32 accum).
// 128 ch: warp per segment, uint2 per lane.  64 ch: 16-lane group per segment.
// ---------------------------------------------------------------------------
// e1h[h] = binv[h] * sum x_h[n]
__global__ void __launch_bounds__(256) n2h1_k() {
    int w = blockIdx.x * 8 + (threadIdx.x >> 5);
    if (w >= N_HEDGESC) return;
    int lane = threadIdx.x & 31;
    int base = g_hoff[w], end = g_hoff[w + 1];
    float4 a0 = make_float4(0.f, 0.f, 0.f, 0.f);
    float4 a1 = make_float4(0.f, 0.f, 0.f, 0.f);
    int j = base;
    for (; j + 4 <= end; j += 4) {
        int n0 = __ldg(g_hlist + j + 0);
        int n1 = __ldg(g_hlist + j + 1);
        int n2 = __ldg(g_hlist + j + 2);
        int n3 = __ldg(g_hlist + j + 3);
        uint2 u0 = __ldg(reinterpret_cast<const uint2*>(g_xh + (size_t)n0 * IN_C) + lane);
        uint2 u1 = __ldg(reinterpret_cast<const uint2*>(g_xh + (size_t)n1 * IN_C) + lane);
        uint2 u2 = __ldg(reinterpret_cast<const uint2*>(g_xh + (size_t)n2 * IN_C) + lane);
        uint2 u3 = __ldg(reinterpret_cast<const uint2*>(g_xh + (size_t)n3 * IN_C) + lane);
        acc_h2(a0, u0); acc_h2(a1, u1); acc_h2(a0, u2); acc_h2(a1, u3);
    }
    for (; j < end; j++) {
        int n0 = __ldg(g_hlist + j);
        uint2 u0 = __ldg(reinterpret_cast<const uint2*>(g_xh + (size_t)n0 * IN_C) + lane);
        acc_h2(a0, u0);
    }
    float bi = g_binv[w];
    reinterpret_cast<uint2*>(g_e1h + (size_t)w * IN_C)[lane] =
        pack_h2((a0.x + a1.x) * bi, (a0.y + a1.y) * bi,
                (a0.z + a1.z) * bi, (a0.w + a1.w) * bi);
}

// a1h[n] = dinv[n] * sum e1h[h]
__global__ void __launch_bounds__(256) h2n1_k() {
    int w = blockIdx.x * 8 + (threadIdx.x >> 5);
    if (w >= N_NODESC) return;
    int lane = threadIdx.x & 31;
    int base = g_noff[w], end = g_noff[w + 1];
    float4 a0 = make_float4(0.f, 0.f, 0.f, 0.f);
    float4 a1 = make_float4(0.f, 0.f, 0.f, 0.f);
    int j = base;
    for (; j + 4 <= end; j += 4) {
        int h0 = __ldg(g_nlist + j + 0);
        int h1 = __ldg(g_nlist + j + 1);
        int h2 = __ldg(g_nlist + j + 2);
        int h3 = __ldg(g_nlist + j + 3);
        uint2 u0 = __ldg(reinterpret_cast<const uint2*>(g_e1h + (size_t)h0 * IN_C) + lane);
        uint2 u1 = __ldg(reinterpret_cast<const uint2*>(g_e1h + (size_t)h1 * IN_C) + lane);
        uint2 u2 = __ldg(reinterpret_cast<const uint2*>(g_e1h + (size_t)h2 * IN_C) + lane);
        uint2 u3 = __ldg(reinterpret_cast<const uint2*>(g_e1h + (size_t)h3 * IN_C) + lane);
        acc_h2(a0, u0); acc_h2(a1, u1); acc_h2(a0, u2); acc_h2(a1, u3);
    }
    for (; j < end; j++) {
        int h0 = __ldg(g_nlist + j);
        uint2 u0 = __ldg(reinterpret_cast<const uint2*>(g_e1h + (size_t)h0 * IN_C) + lane);
        acc_h2(a0, u0);
    }
    float di = g_dinv[w];
    reinterpret_cast<uint2*>(g_a1h + (size_t)w * IN_C)[lane] =
        pack_h2((a0.x + a1.x) * di, (a0.y + a1.y) * di,
                (a0.z + a1.z) * di, (a0.w + a1.w) * di);
}

// e2h[h] = binv[h] * sum y2h[n]   (64 ch)
__global__ void __launch_bounds__(256) n2h2_k() {
    int g = blockIdx.x * 16 + (threadIdx.x >> 4);
    if (g >= N_HEDGESC) return;
    int lane = threadIdx.x & 15;
    int base = g_hoff[g], end = g_hoff[g + 1];
    float4 a0 = make_float4(0.f, 0.f, 0.f, 0.f);
    float4 a1 = make_float4(0.f, 0.f, 0.f, 0.f);
    int j = base;
    for (; j + 4 <= end; j += 4) {
        int n0 = __ldg(g_hlist + j + 0);
        int n1 = __ldg(g_hlist + j + 1);
        int n2 = __ldg(g_hlist + j + 2);
        int n3 = __ldg(g_hlist + j + 3);
        uint2 u0 = __ldg(reinterpret_cast<const uint2*>(g_y2h + (size_t)n0 * D2C) + lane);
        uint2 u1 = __ldg(reinterpret_cast<const uint2*>(g_y2h + (size_t)n1 * D2C) + lane);
        uint2 u2 = __ldg(reinterpret_cast<const uint2*>(g_y2h + (size_t)n2 * D2C) + lane);
        uint2 u3 = __ldg(reinterpret_cast<const uint2*>(g_y2h + (size_t)n3 * D2C) + lane);
        acc_h2(a0, u0); acc_h2(a1, u1); acc_h2(a0, u2); acc_h2(a1, u3);
    }
    for (; j < end; j++) {
        int n0 = __ldg(g_hlist + j);
        uint2 u0 = __ldg(reinterpret_cast<const uint2*>(g_y2h + (size_t)n0 * D2C) + lane);
        acc_h2(a0, u0);
    }
    float bi = g_binv[g];
    reinterpret_cast<uint2*>(g_e2h + (size_t)g * D2C)[lane] =
        pack_h2((a0.x + a1.x) * bi, (a0.y + a1.y) * bi,
                (a0.z + a1.z) * bi, (a0.w + a1.w) * bi);
}

// out[n] = relu(dinv[n] * sum e2h[h] + b2)   (fp32 output, fused epilogue)
__global__ void __launch_bounds__(256) h2n2_k(const float* __restrict__ b2,
                                              float* __restrict__ out) {
    int g = blockIdx.x * 16 + (threadIdx.x >> 4);
    if (g >= N_NODESC) return;
    int lane = threadIdx.x & 15;
    int base = g_noff[g], end = g_noff[g + 1];
    float4 a0 = make_float4(0.f, 0.f, 0.f, 0.f);
    float4 a1 = make_float4(0.f, 0.f, 0.f, 0.f);
    int j = base;
    for (; j + 4 <= end; j += 4) {
        int h0 = __ldg(g_nlist + j + 0);
        int h1 = __ldg(g_nlist + j + 1);
        int h2 = __ldg(g_nlist + j + 2);
        int h3 = __ldg(g_nlist + j + 3);
        uint2 u0 = __ldg(reinterpret_cast<const uint2*>(g_e2h + (size_t)h0 * D2C) + lane);
        uint2 u1 = __ldg(reinterpret_cast<const uint2*>(g_e2h + (size_t)h1 * D2C) + lane);
        uint2 u2 = __ldg(reinterpret_cast<const uint2*>(g_e2h + (size_t)h2 * D2C) + lane);
        uint2 u3 = __ldg(reinterpret_cast<const uint2*>(g_e2h + (size_t)h3 * D2C) + lane);
        acc_h2(a0, u0); acc_h2(a1, u1); acc_h2(a0, u2); acc_h2(a1, u3);
    }
    for (; j < end; j++) {
        int h0 = __ldg(g_nlist + j);
        uint2 u0 = __ldg(reinterpret_cast<const uint2*>(g_e2h + (size_t)h0 * D2C) + lane);
        acc_h2(a0, u0);
    }
    float di = g_dinv[g];
    float4 b = __ldg(reinterpret_cast<const float4*>(b2) + lane);
    float4 r;
    r.x = fmaxf(fmaf(a0.x + a1.x, di, b.x), 0.f);
    r.y = fmaxf(fmaf(a0.y + a1.y, di, b.y), 0.f);
    r.z = fmaxf(fmaf(a0.z + a1.z, di, b.z), 0.f);
    r.w = fmaxf(fmaf(a0.w + a1.w, di, b.w), 0.f);
    reinterpret_cast<float4*>(out + (size_t)g * D2C)[lane] = r;
}

// ---------------------------------------------------------------------------
// fp16 tensor-core GEMM (R6 verified).
// ---------------------------------------------------------------------------
__device__ __forceinline__ void mma_f16(float& d0, float& d1, float& d2, float& d3,
                                        uint32_t a0, uint32_t a1, uint32_t a2, uint32_t a3,
                                        uint32_t b0, uint32_t b1) {
    asm volatile(
        "mma.sync.aligned.m16n8k16.row.col.f32.f16.f16.f32 "
        "{%0,%1,%2,%3}, {%4,%5,%6,%7}, {%8,%9}, {%0,%1,%2,%3};"
        : "+f"(d0), "+f"(d1), "+f"(d2), "+f"(d3)
        : "r"(a0), "r"(a1), "r"(a2), "r"(a3), "r"(b0), "r"(b1));
}

template <int BM, int BN, int BK, int WARPS_M, int WARPS_N, bool EPI>
__device__ __forceinline__ void gemm_f16_body(const __half* __restrict__ A,
                                              const __half* __restrict__ Bt,
                                              const float* __restrict__ bias,
                                              __half* __restrict__ C,
                                              int M, int N, int K) {
    constexpr int THREADS = WARPS_M * WARPS_N * 32;
    constexpr int WM = BM / WARPS_M;
    constexpr int WN = BN / WARPS_N;
    constexpr int MI = WM / 16;
    constexpr int NI = WN / 8;
    constexpr int PAD = 8;
    constexpr int AV = (BM * BK / 8) / THREADS;
    constexpr int BV = (BN * BK / 8) / THREADS;

    __shared__ __align__(16) __half As[BM][BK + PAD];
    __shared__ __align__(16) __half Bs[BN][BK + PAD];

    const int tid  = threadIdx.x;
    const int warp = tid >> 5;
    const int lane = tid & 31;
    const int wm   = warp / WARPS_N;
    const int wn   = warp % WARPS_N;
    const int row0 = blockIdx.y * BM;
    const int col0 = blockIdx.x * BN;
    const int lq   = lane >> 2;
    const int lr   = lane & 3;

    float acc[MI][NI][4];
#pragma unroll
    for (int i = 0; i < MI; i++)
#pragma unroll
        for (int j = 0; j < NI; j++)
#pragma unroll
            for (int c = 0; c < 4; c++) acc[i][j][c] = 0.f;

    for (int kt = 0; kt < K; kt += BK) {
#pragma unroll
        for (int i = 0; i < AV; i++) {
            int idx = tid + i * THREADS;
            int m   = idx / (BK / 8);
            int kc  = (idx % (BK / 8)) * 8;
            int grow = row0 + m;
            uint4 v = make_uint4(0, 0, 0, 0);
            if (grow < M)
                v = __ldg(reinterpret_cast<const uint4*>(A + (size_t)grow * K + kt + kc));
            *reinterpret_cast<uint4*>(&As[m][kc]) = v;
        }
#pragma unroll
        for (int i = 0; i < BV; i++) {
            int idx = tid + i * THREADS;
            int n   = idx / (BK / 8);
            int kc  = (idx % (BK / 8)) * 8;
            uint4 v = __ldg(reinterpret_cast<const uint4*>(Bt + (size_t)(col0 + n) * K + kt + kc));
            *reinterpret_cast<uint4*>(&Bs[n][kc]) = v;
        }
        __syncthreads();

#pragma unroll
        for (int ks = 0; ks < BK; ks += 16) {
            uint32_t af[MI][4];
            uint32_t bf[NI][2];
#pragma unroll
            for (int i = 0; i < MI; i++) {
                int m0 = wm * WM + i * 16;
                af[i][0] = *reinterpret_cast<const uint32_t*>(&As[m0 + lq    ][ks + 2 * lr    ]);
                af[i][1] = *reinterpret_cast<const uint32_t*>(&As[m0 + lq + 8][ks + 2 * lr    ]);
                af[i][2] = *reinterpret_cast<const uint32_t*>(&As[m0 + lq    ][ks + 2 * lr + 8]);
                af[i][3] = *reinterpret_cast<const uint32_t*>(&As[m0 + lq + 8][ks + 2 * lr + 8]);
            }
#pragma unroll
            for (int j = 0; j < NI; j++) {
                int n0 = wn * WN + j * 8;
                bf[j][0] = *reinterpret_cast<const uint32_t*>(&Bs[n0 + lq][ks + 2 * lr    ]);
                bf[j][1] = *reinterpret_cast<const uint32_t*>(&Bs[n0 + lq][ks + 2 * lr + 8]);
            }
#pragma unroll
            for (int i = 0; i < MI; i++)
#pragma unroll
                for (int j = 0; j < NI; j++)
                    mma_f16(acc[i][j][0], acc[i][j][1], acc[i][j][2], acc[i][j][3],
                            af[i][0], af[i][1], af[i][2], af[i][3],
                            bf[j][0], bf[j][1]);
        }
        __syncthreads();
    }

#pragma unroll
    for (int i = 0; i < MI; i++) {
#pragma unroll
        for (int j = 0; j < NI; j++) {
            int row = row0 + wm * WM + i * 16 + lq;
            int col = col0 + wn * WN + j * 8 + 2 * lr;
            float2 v0 = make_float2(acc[i][j][0], acc[i][j][1]);
            float2 v1 = make_float2(acc[i][j][2], acc[i][j][3]);
            if (EPI) {
                float b0 = bias[col], b1 = bias[col + 1];
                v0.x = fmaxf(v0.x + b0, 0.f);
                v0.y = fmaxf(v0.y + b1, 0.f);
                v1.x = fmaxf(v1.x + b0, 0.f);
                v1.y = fmaxf(v1.y + b1, 0.f);
            }
            if (row < M)
                *reinterpret_cast<__half2*>(&C[(size_t)row * N + col]) =
                    __floats2half2_rn(v0.x, v0.y);
            if (row + 8 < M)
                *reinterpret_cast<__half2*>(&C[(size_t)(row + 8) * N + col]) =
                    __floats2half2_rn(v1.x, v1.y);
        }
    }
}

// GEMM1: g_hh = relu(g_a1h @ W1 + b1)   [50000x128]@[128x256]
__global__ void __launch_bounds__(256) gemm1_k(const float* __restrict__ b1) {
    gemm_f16_body<128, 128, 32, 2, 4, true>(g_a1h, g_w1h, b1, g_hh, N_NODESC, D1C, IN_C);
}

// GEMM2: g_y2h = g_hh @ W2   [50000x256]@[256x64]
__global__ void __launch_bounds__(256) gemm2_k() {
    gemm_f16_body<128, 64, 32, 4, 2, false>(g_hh, g_w2h, nullptr, g_y2h, N_NODESC, D2C, D1C);
}

// ---------------------------------------------------------------------------
// Launch (10 kernels)
// ---------------------------------------------------------------------------
extern "C" void kernel_launch(void* const* d_in, const int* in_sizes, int n_in,
                              void* d_out, int out_size) {
    const float* x    = (const float*)d_in[0];
    const int*   edge = (const int*)d_in[1];
    const float* W1   = (const float*)d_in[2];
    const float* b1   = (const float*)d_in[3];
    const float* W2   = (const float*)d_in[4];
    const float* b2   = (const float*)d_in[5];
    float*       out  = (float*)d_out;

    const int* ni = edge;          // edge[0] = node_idx
    const int* hi = edge + NNZC;   // edge[1] = hedge_idx

    // conversions + zero + barrier reset; CSR construction
    cvt_k<<<1024, 256>>>(x, W1, W2);
    hist_k<<<(NNZC / 2 + 255) / 256, 256>>>(ni, hi);
    scan_k<<<NBLK, 256>>>();
    build_k<<<(NNZC / 2 + 255) / 256, 256>>>(ni, hi);

    // Layer 1 aggregation at 128 channels (fp16 gather)
    n2h1_k<<<(N_HEDGESC + 7) / 8, 256>>>();
    h2n1_k<<<(N_NODESC + 7) / 8, 256>>>();

    // h = relu(agg1 @ W1 + b1) ; y2 = h @ W2   (fp16 tensor cores)
    {
        dim3 g1(D1C / 128, (N_NODESC + 127) / 128);
        gemm1_k<<<g1, 256>>>(b1);
        dim3 g2(D2C / 64, (N_NODESC + 127) / 128);
        gemm2_k<<<g2, 256>>>();
    }

    // Layer 2 aggregation at 64 channels (fp16 gather) + fused final epilogue
    n2h2_k<<<(N_HEDGESC + 15) / 16, 256>>>();
    h2n2_k<<<(N_NODESC + 15) / 16, 256>>>(b2, out);
}

// round 10
// speedup vs baseline: 1.4677x; 1.0229x over previous
#include <cuda_runtime.h>
#include <cuda_fp16.h>
#include <cstdint>
#include <cstddef>

// Problem constants (fixed shapes for Hgnn_17394617548829)
#define N_NODESC 50000
#define N_HEDGESC 5000
#define NNZC 800000
#define IN_C 128
#define D1C 256
#define D2C 64

// Scan chunking: 256 elements per block
#define NBLK_H 20    // ceil(5000/256)
#define NBLK_N 196   // ceil(50000/256)
#define NBLK   216

// ---------------------------------------------------------------------------
// Scratch (static device globals; no allocation anywhere).
// INVARIANT: g_deg / g_cnt are all-zero at kernel_launch entry.
//   - first run: .bss zero-initialization
//   - later runs: zeroed at the tail of h2n2_k (last kernel of previous run)
// ---------------------------------------------------------------------------
__device__ __half g_xh  [(size_t)N_NODESC * IN_C];   // 12.8 MB (x in fp16)
__device__ __half g_e1h [(size_t)N_HEDGESC * IN_C];  // 1.28 MB
__device__ __half g_a1h [(size_t)N_NODESC * IN_C];   // 12.8 MB (agg1 fp16)
__device__ __half g_hh  [(size_t)N_NODESC * D1C];    // 25.6 MB
__device__ __half g_y2h [(size_t)N_NODESC * D2C];    // 6.4 MB
__device__ __half g_e2h [(size_t)N_HEDGESC * D2C];   // 0.64 MB
__device__ __half g_w1h [(size_t)D1C * IN_C];        // W1^T [N=256][K=128]
__device__ __half g_w2h [(size_t)D2C * D1C];         // W2^T [N=64][K=256]
__device__ int   g_cnt [N_HEDGESC];
__device__ int   g_deg [N_NODESC];
__device__ int   g_hoff[N_HEDGESC + 1];
__device__ int   g_noff[N_NODESC + 1];
__device__ int   g_hcur[N_HEDGESC];
__device__ int   g_ncur[N_NODESC];
__device__ unsigned short g_hlist[NNZC];             // node ids (fit in u16)
__device__ unsigned short g_nlist[NNZC];             // hedge ids (fit in u16)
__device__ float g_dinv[N_NODESC];
__device__ float g_binv[N_HEDGESC];
__device__ int   g_part[NBLK];
__device__ int   g_partoff[NBLK];
__device__ int   g_bar0;            // grid-barrier counters (reset in cvt_k)
__device__ int   g_bar1;

// ---------------------------------------------------------------------------
// fp16 helpers
// ---------------------------------------------------------------------------
__device__ __forceinline__ void acc_h2(float4& a, uint2 u) {
    __half2 p0 = *reinterpret_cast<__half2*>(&u.x);
    __half2 p1 = *reinterpret_cast<__half2*>(&u.y);
    float2 f0 = __half22float2(p0);
    float2 f1 = __half22float2(p1);
    a.x += f0.x; a.y += f0.y; a.z += f1.x; a.w += f1.y;
}

__device__ __forceinline__ uint2 pack_h2(float x, float y, float z, float w) {
    __half2 h0 = __floats2half2_rn(x, y);
    __half2 h1 = __floats2half2_rn(z, w);
    uint2 u;
    u.x = *reinterpret_cast<unsigned*>(&h0);
    u.y = *reinterpret_cast<unsigned*>(&h1);
    return u;
}

// ---------------------------------------------------------------------------
// 0. FUSED: degree histograms (fire-and-forget REDs, counters pre-zeroed) +
//    fp16 conversions + grid-barrier reset. The REDs overlap with the
//    streaming conversion traffic.
// ---------------------------------------------------------------------------
__global__ void __launch_bounds__(256) cvt_k(const float* __restrict__ x,
                                             const float* __restrict__ W1,
                                             const float* __restrict__ W2,
                                             const int* __restrict__ ni,
                                             const int* __restrict__ hi) {
    int i = blockIdx.x * blockDim.x + threadIdx.x;
    int stride = gridDim.x * blockDim.x;
    if (i == 0) { g_bar0 = 0; g_bar1 = 0; }

    // histogram (atomics without return -> REDG, no scoreboard stall)
    for (int j = i; j < NNZC / 2; j += stride) {
        int2 nn = *reinterpret_cast<const int2*>(ni + 2 * j);
        int2 hh = *reinterpret_cast<const int2*>(hi + 2 * j);
        atomicAdd(&g_deg[nn.x], 1);
        atomicAdd(&g_deg[nn.y], 1);
        atomicAdd(&g_cnt[hh.x], 1);
        atomicAdd(&g_cnt[hh.y], 1);
    }

    const float4* x4 = reinterpret_cast<const float4*>(x);
    uint2* xh2 = reinterpret_cast<uint2*>(g_xh);
    for (int j = i; j < N_NODESC * IN_C / 4; j += stride) {
        float4 v = x4[j];
        xh2[j] = pack_h2(v.x, v.y, v.z, v.w);
    }
    for (int j = i; j < D1C * IN_C; j += stride) {
        int n = j / IN_C, k = j % IN_C;
        g_w1h[j] = __float2half(W1[(size_t)k * D1C + n]);
    }
    for (int j = i; j < D2C * D1C; j += stride) {
        int n = j / D1C, k = j % D1C;
        g_w2h[j] = __float2half(W2[(size_t)k * D2C + n]);
    }
}

// ---------------------------------------------------------------------------
// 1. fused segmented exclusive scan (one kernel, grid barrier; phase 2 in
//    block-0 shared memory). 216 blocks <= 1 wave -> no deadlock.
// ---------------------------------------------------------------------------
__global__ void __launch_bounds__(256) scan_k() {
    __shared__ int sh[256];
    __shared__ int shp[NBLK];
    const int b   = blockIdx.x;
    const int tid = threadIdx.x;
    const int* src; int* off; int* cur; float* inv;
    int idx, n;
    if (b < NBLK_H) {
        src = g_cnt; off = g_hoff; cur = g_hcur; inv = g_binv;
        idx = b * 256 + tid; n = N_HEDGESC;
    } else {
        src = g_deg; off = g_noff; cur = g_ncur; inv = g_dinv;
        idx = (b - NBLK_H) * 256 + tid; n = N_NODESC;
    }
    int v = (idx < n) ? src[idx] : 0;

    // --- phase 1: block-local inclusive scan + publish block total ---
    sh[tid] = v;
    __syncthreads();
    for (int d = 1; d < 256; d <<= 1) {
        int t = (tid >= d) ? sh[tid - d] : 0;
        __syncthreads();
        sh[tid] += t;
        __syncthreads();
    }
    int incl = sh[tid];
    if (tid == 255) {
        g_part[b] = incl;
        __threadfence();
        atomicAdd(&g_bar0, 1);
    }

    // --- phase 2: block 0 scans the 216 partials in shared memory ---
    if (b == 0) {
        if (tid == 0) {
            while (atomicAdd(&g_bar0, 0) < NBLK) __nanosleep(32);
        }
        __syncthreads();
        __threadfence();
        if (tid < NBLK) shp[tid] = g_part[tid];
        __syncthreads();
        if (tid == 0) {
            int run = 0;
            for (int i = 0; i < NBLK_H; i++) { int c = shp[i]; shp[i] = run; run += c; }
            run = 0;
            for (int i = NBLK_H; i < NBLK; i++) { int c = shp[i]; shp[i] = run; run += c; }
        }
        __syncthreads();
        if (tid < NBLK) g_partoff[tid] = shp[tid];
        __threadfence();
        __syncthreads();
        if (tid == 0) atomicExch(&g_bar1, 1);
    }
    if (tid == 0) {
        while (atomicAdd(&g_bar1, 0) == 0) __nanosleep(32);
    }
    __syncthreads();
    __threadfence();

    // --- phase 3: fill offsets / cursors / inverse degrees ---
    if (idx < n) {
        int excl = incl - v + g_partoff[b];
        off[idx] = excl;
        cur[idx] = excl;
        inv[idx] = (v > 0) ? 1.0f / (float)v : 0.0f;
    }
    if (b == 0 && tid == 0) {
        g_hoff[N_HEDGESC] = NNZC;
        g_noff[N_NODESC]  = NNZC;
    }
}

// ---------------------------------------------------------------------------
// 2. scatter edges into both CSR member lists (2 edges/thread, u16 payloads)
// ---------------------------------------------------------------------------
__global__ void __launch_bounds__(256) build_k(const int* __restrict__ ni,
                                               const int* __restrict__ hi) {
    int i = blockIdx.x * blockDim.x + threadIdx.x;
    if (2 * i >= NNZC) return;
    int2 nn = *reinterpret_cast<const int2*>(ni + 2 * i);
    int2 hh = *reinterpret_cast<const int2*>(hi + 2 * i);
    int p0 = atomicAdd(&g_hcur[hh.x], 1);
    int p1 = atomicAdd(&g_hcur[hh.y], 1);
    int q0 = atomicAdd(&g_ncur[nn.x], 1);
    int q1 = atomicAdd(&g_ncur[nn.y], 1);
    g_hlist[p0] = (unsigned short)nn.x;
    g_hlist[p1] = (unsigned short)nn.y;
    g_nlist[q0] = (unsigned short)hh.x;
    g_nlist[q1] = (unsigned short)hh.y;
}

// ---------------------------------------------------------------------------
// Gather kernels — R6-proven structure, u16 index loads.
// 128 ch: warp per segment, uint2 per lane.  64 ch: 16-lane group per segment.
// ---------------------------------------------------------------------------
// e1h[h] = binv[h] * sum x_h[n]
__global__ void __launch_bounds__(256) n2h1_k() {
    int w = blockIdx.x * 8 + (threadIdx.x >> 5);
    if (w >= N_HEDGESC) return;
    int lane = threadIdx.x & 31;
    int base = g_hoff[w], end = g_hoff[w + 1];
    float4 a0 = make_float4(0.f, 0.f, 0.f, 0.f);
    float4 a1 = make_float4(0.f, 0.f, 0.f, 0.f);
    int j = base;
    for (; j + 4 <= end; j += 4) {
        int n0 = __ldg(g_hlist + j + 0);
        int n1 = __ldg(g_hlist + j + 1);
        int n2 = __ldg(g_hlist + j + 2);
        int n3 = __ldg(g_hlist + j + 3);
        uint2 u0 = __ldg(reinterpret_cast<const uint2*>(g_xh + (size_t)n0 * IN_C) + lane);
        uint2 u1 = __ldg(reinterpret_cast<const uint2*>(g_xh + (size_t)n1 * IN_C) + lane);
        uint2 u2 = __ldg(reinterpret_cast<const uint2*>(g_xh + (size_t)n2 * IN_C) + lane);
        uint2 u3 = __ldg(reinterpret_cast<const uint2*>(g_xh + (size_t)n3 * IN_C) + lane);
        acc_h2(a0, u0); acc_h2(a1, u1); acc_h2(a0, u2); acc_h2(a1, u3);
    }
    for (; j < end; j++) {
        int n0 = __ldg(g_hlist + j);
        uint2 u0 = __ldg(reinterpret_cast<const uint2*>(g_xh + (size_t)n0 * IN_C) + lane);
        acc_h2(a0, u0);
    }
    float bi = g_binv[w];
    reinterpret_cast<uint2*>(g_e1h + (size_t)w * IN_C)[lane] =
        pack_h2((a0.x + a1.x) * bi, (a0.y + a1.y) * bi,
                (a0.z + a1.z) * bi, (a0.w + a1.w) * bi);
}

// a1h[n] = dinv[n] * sum e1h[h]
__global__ void __launch_bounds__(256) h2n1_k() {
    int w = blockIdx.x * 8 + (threadIdx.x >> 5);
    if (w >= N_NODESC) return;
    int lane = threadIdx.x & 31;
    int base = g_noff[w], end = g_noff[w + 1];
    float4 a0 = make_float4(0.f, 0.f, 0.f, 0.f);
    float4 a1 = make_float4(0.f, 0.f, 0.f, 0.f);
    int j = base;
    for (; j + 4 <= end; j += 4) {
        int h0 = __ldg(g_nlist + j + 0);
        int h1 = __ldg(g_nlist + j + 1);
        int h2 = __ldg(g_nlist + j + 2);
        int h3 = __ldg(g_nlist + j + 3);
        uint2 u0 = __ldg(reinterpret_cast<const uint2*>(g_e1h + (size_t)h0 * IN_C) + lane);
        uint2 u1 = __ldg(reinterpret_cast<const uint2*>(g_e1h + (size_t)h1 * IN_C) + lane);
        uint2 u2 = __ldg(reinterpret_cast<const uint2*>(g_e1h + (size_t)h2 * IN_C) + lane);
        uint2 u3 = __ldg(reinterpret_cast<const uint2*>(g_e1h + (size_t)h3 * IN_C) + lane);
        acc_h2(a0, u0); acc_h2(a1, u1); acc_h2(a0, u2); acc_h2(a1, u3);
    }
    for (; j < end; j++) {
        int h0 = __ldg(g_nlist + j);
        uint2 u0 = __ldg(reinterpret_cast<const uint2*>(g_e1h + (size_t)h0 * IN_C) + lane);
        acc_h2(a0, u0);
    }
    float di = g_dinv[w];
    reinterpret_cast<uint2*>(g_a1h + (size_t)w * IN_C)[lane] =
        pack_h2((a0.x + a1.x) * di, (a0.y + a1.y) * di,
                (a0.z + a1.z) * di, (a0.w + a1.w) * di);
}

// e2h[h] = binv[h] * sum y2h[n]   (64 ch)
__global__ void __launch_bounds__(256) n2h2_k() {
    int g = blockIdx.x * 16 + (threadIdx.x >> 4);
    if (g >= N_HEDGESC) return;
    int lane = threadIdx.x & 15;
    int base = g_hoff[g], end = g_hoff[g + 1];
    float4 a0 = make_float4(0.f, 0.f, 0.f, 0.f);
    float4 a1 = make_float4(0.f, 0.f, 0.f, 0.f);
    int j = base;
    for (; j + 4 <= end; j += 4) {
        int n0 = __ldg(g_hlist + j + 0);
        int n1 = __ldg(g_hlist + j + 1);
        int n2 = __ldg(g_hlist + j + 2);
        int n3 = __ldg(g_hlist + j + 3);
        uint2 u0 = __ldg(reinterpret_cast<const uint2*>(g_y2h + (size_t)n0 * D2C) + lane);
        uint2 u1 = __ldg(reinterpret_cast<const uint2*>(g_y2h + (size_t)n1 * D2C) + lane);
        uint2 u2 = __ldg(reinterpret_cast<const uint2*>(g_y2h + (size_t)n2 * D2C) + lane);
        uint2 u3 = __ldg(reinterpret_cast<const uint2*>(g_y2h + (size_t)n3 * D2C) + lane);
        acc_h2(a0, u0); acc_h2(a1, u1); acc_h2(a0, u2); acc_h2(a1, u3);
    }
    for (; j < end; j++) {
        int n0 = __ldg(g_hlist + j);
        uint2 u0 = __ldg(reinterpret_cast<const uint2*>(g_y2h + (size_t)n0 * D2C) + lane);
        acc_h2(a0, u0);
    }
    float bi = g_binv[g];
    reinterpret_cast<uint2*>(g_e2h + (size_t)g * D2C)[lane] =
        pack_h2((a0.x + a1.x) * bi, (a0.y + a1.y) * bi,
                (a0.z + a1.z) * bi, (a0.w + a1.w) * bi);
}

// out[n] = relu(dinv[n] * sum e2h[h] + b2); tail restores the zero-counter
// invariant for the next kernel_launch call.
__global__ void __launch_bounds__(256) h2n2_k(const float* __restrict__ b2,
                                              float* __restrict__ out) {
    int g = blockIdx.x * 16 + (threadIdx.x >> 4);
    if (g < N_NODESC) {
        int lane = threadIdx.x & 15;
        int base = g_noff[g], end = g_noff[g + 1];
        float4 a0 = make_float4(0.f, 0.f, 0.f, 0.f);
        float4 a1 = make_float4(0.f, 0.f, 0.f, 0.f);
        int j = base;
        for (; j + 4 <= end; j += 4) {
            int h0 = __ldg(g_nlist + j + 0);
            int h1 = __ldg(g_nlist + j + 1);
            int h2 = __ldg(g_nlist + j + 2);
            int h3 = __ldg(g_nlist + j + 3);
            uint2 u0 = __ldg(reinterpret_cast<const uint2*>(g_e2h + (size_t)h0 * D2C) + lane);
            uint2 u1 = __ldg(reinterpret_cast<const uint2*>(g_e2h + (size_t)h1 * D2C) + lane);
            uint2 u2 = __ldg(reinterpret_cast<const uint2*>(g_e2h + (size_t)h2 * D2C) + lane);
            uint2 u3 = __ldg(reinterpret_cast<const uint2*>(g_e2h + (size_t)h3 * D2C) + lane);
            acc_h2(a0, u0); acc_h2(a1, u1); acc_h2(a0, u2); acc_h2(a1, u3);
        }
        for (; j < end; j++) {
            int h0 = __ldg(g_nlist + j);
            uint2 u0 = __ldg(reinterpret_cast<const uint2*>(g_e2h + (size_t)h0 * D2C) + lane);
            acc_h2(a0, u0);
        }
        float di = g_dinv[g];
        float4 b = __ldg(reinterpret_cast<const float4*>(b2) + lane);
        float4 r;
        r.x = fmaxf(fmaf(a0.x + a1.x, di, b.x), 0.f);
        r.y = fmaxf(fmaf(a0.y + a1.y, di, b.y), 0.f);
        r.z = fmaxf(fmaf(a0.z + a1.z, di, b.z), 0.f);
        r.w = fmaxf(fmaf(a0.w + a1.w, di, b.w), 0.f);
        reinterpret_cast<float4*>(out + (size_t)g * D2C)[lane] = r;
    }
    // restore invariant: counters zero for next launch
    int t = blockIdx.x * blockDim.x + threadIdx.x;
    int stride = gridDim.x * blockDim.x;
    for (int j = t; j < N_NODESC; j += stride) g_deg[j] = 0;
    for (int j = t; j < N_HEDGESC; j += stride) g_cnt[j] = 0;
}

// ---------------------------------------------------------------------------
// fp16 tensor-core GEMM (R6 verified).
// ---------------------------------------------------------------------------
__device__ __forceinline__ void mma_f16(float& d0, float& d1, float& d2, float& d3,
                                        uint32_t a0, uint32_t a1, uint32_t a2, uint32_t a3,
                                        uint32_t b0, uint32_t b1) {
    asm volatile(
        "mma.sync.aligned.m16n8k16.row.col.f32.f16.f16.f32 "
        "{%0,%1,%2,%3}, {%4,%5,%6,%7}, {%8,%9}, {%0,%1,%2,%3};"
        : "+f"(d0), "+f"(d1), "+f"(d2), "+f"(d3)
        : "r"(a0), "r"(a1), "r"(a2), "r"(a3), "r"(b0), "r"(b1));
}

template <int BM, int BN, int BK, int WARPS_M, int WARPS_N, bool EPI>
__device__ __forceinline__ void gemm_f16_body(const __half* __restrict__ A,
                                              const __half* __restrict__ Bt,
                                              const float* __restrict__ bias,
                                              __half* __restrict__ C,
                                              int M, int N, int K) {
    constexpr int THREADS = WARPS_M * WARPS_N * 32;
    constexpr int WM = BM / WARPS_M;
    constexpr int WN = BN / WARPS_N;
    constexpr int MI = WM / 16;
    constexpr int NI = WN / 8;
    constexpr int PAD = 8;
    constexpr int AV = (BM * BK / 8) / THREADS;
    constexpr int BV = (BN * BK / 8) / THREADS;

    __shared__ __align__(16) __half As[BM][BK + PAD];
    __shared__ __align__(16) __half Bs[BN][BK + PAD];

    const int tid  = threadIdx.x;
    const int warp = tid >> 5;
    const int lane = tid & 31;
    const int wm   = warp / WARPS_N;
    const int wn   = warp % WARPS_N;
    const int row0 = blockIdx.y * BM;
    const int col0 = blockIdx.x * BN;
    const int lq   = lane >> 2;
    const int lr   = lane & 3;

    float acc[MI][NI][4];
#pragma unroll
    for (int i = 0; i < MI; i++)
#pragma unroll
        for (int j = 0; j < NI; j++)
#pragma unroll
            for (int c = 0; c < 4; c++) acc[i][j][c] = 0.f;

    for (int kt = 0; kt < K; kt += BK) {
#pragma unroll
        for (int i = 0; i < AV; i++) {
            int idx = tid + i * THREADS;
            int m   = idx / (BK / 8);
            int kc  = (idx % (BK / 8)) * 8;
            int grow = row0 + m;
            uint4 v = make_uint4(0, 0, 0, 0);
            if (grow < M)
                v = __ldg(reinterpret_cast<const uint4*>(A + (size_t)grow * K + kt + kc));
            *reinterpret_cast<uint4*>(&As[m][kc]) = v;
        }
#pragma unroll
        for (int i = 0; i < BV; i++) {
            int idx = tid + i * THREADS;
            int n   = idx / (BK / 8);
            int kc  = (idx % (BK / 8)) * 8;
            uint4 v = __ldg(reinterpret_cast<const uint4*>(Bt + (size_t)(col0 + n) * K + kt + kc));
            *reinterpret_cast<uint4*>(&Bs[n][kc]) = v;
        }
        __syncthreads();

#pragma unroll
        for (int ks = 0; ks < BK; ks += 16) {
            uint32_t af[MI][4];
            uint32_t bf[NI][2];
#pragma unroll
            for (int i = 0; i < MI; i++) {
                int m0 = wm * WM + i * 16;
                af[i][0] = *reinterpret_cast<const uint32_t*>(&As[m0 + lq    ][ks + 2 * lr    ]);
                af[i][1] = *reinterpret_cast<const uint32_t*>(&As[m0 + lq + 8][ks + 2 * lr    ]);
                af[i][2] = *reinterpret_cast<const uint32_t*>(&As[m0 + lq    ][ks + 2 * lr + 8]);
                af[i][3] = *reinterpret_cast<const uint32_t*>(&As[m0 + lq + 8][ks + 2 * lr + 8]);
            }
#pragma unroll
            for (int j = 0; j < NI; j++) {
                int n0 = wn * WN + j * 8;
                bf[j][0] = *reinterpret_cast<const uint32_t*>(&Bs[n0 + lq][ks + 2 * lr    ]);
                bf[j][1] = *reinterpret_cast<const uint32_t*>(&Bs[n0 + lq][ks + 2 * lr + 8]);
            }
#pragma unroll
            for (int i = 0; i < MI; i++)
#pragma unroll
                for (int j = 0; j < NI; j++)
                    mma_f16(acc[i][j][0], acc[i][j][1], acc[i][j][2], acc[i][j][3],
                            af[i][0], af[i][1], af[i][2], af[i][3],
                            bf[j][0], bf[j][1]);
        }
        __syncthreads();
    }

#pragma unroll
    for (int i = 0; i < MI; i++) {
#pragma unroll
        for (int j = 0; j < NI; j++) {
            int row = row0 + wm * WM + i * 16 + lq;
            int col = col0 + wn * WN + j * 8 + 2 * lr;
            float2 v0 = make_float2(acc[i][j][0], acc[i][j][1]);
            float2 v1 = make_float2(acc[i][j][2], acc[i][j][3]);
            if (EPI) {
                float b0 = bias[col], b1 = bias[col + 1];
                v0.x = fmaxf(v0.x + b0, 0.f);
                v0.y = fmaxf(v0.y + b1, 0.f);
                v1.x = fmaxf(v1.x + b0, 0.f);
                v1.y = fmaxf(v1.y + b1, 0.f);
            }
            if (row < M)
                *reinterpret_cast<__half2*>(&C[(size_t)row * N + col]) =
                    __floats2half2_rn(v0.x, v0.y);
            if (row + 8 < M)
                *reinterpret_cast<__half2*>(&C[(size_t)(row + 8) * N + col]) =
                    __floats2half2_rn(v1.x, v1.y);
        }
    }
}

// GEMM1: g_hh = relu(g_a1h @ W1 + b1)   [50000x128]@[128x256]
__global__ void __launch_bounds__(256) gemm1_k(const float* __restrict__ b1) {
    gemm_f16_body<128, 128, 32, 2, 4, true>(g_a1h, g_w1h, b1, g_hh, N_NODESC, D1C, IN_C);
}

// GEMM2: g_y2h = g_hh @ W2   [50000x256]@[256x64]
__global__ void __launch_bounds__(256) gemm2_k() {
    gemm_f16_body<128, 64, 32, 4, 2, false>(g_hh, g_w2h, nullptr, g_y2h, N_NODESC, D2C, D1C);
}

// ---------------------------------------------------------------------------
// Launch (9 kernels)
// ---------------------------------------------------------------------------
extern "C" void kernel_launch(void* const* d_in, const int* in_sizes, int n_in,
                              void* d_out, int out_size) {
    const float* x    = (const float*)d_in[0];
    const int*   edge = (const int*)d_in[1];
    const float* W1   = (const float*)d_in[2];
    const float* b1   = (const float*)d_in[3];
    const float* W2   = (const float*)d_in[4];
    const float* b2   = (const float*)d_in[5];
    float*       out  = (float*)d_out;

    const int* ni = edge;          // edge[0] = node_idx
    const int* hi = edge + NNZC;   // edge[1] = hedge_idx

    // fused hist + conversions + barrier reset; then scan + scatter
    cvt_k<<<1024, 256>>>(x, W1, W2, ni, hi);
    scan_k<<<NBLK, 256>>>();
    build_k<<<(NNZC / 2 + 255) / 256, 256>>>(ni, hi);

    // Layer 1 aggregation at 128 channels (fp16 gather)
    n2h1_k<<<(N_HEDGESC + 7) / 8, 256>>>();
    h2n1_k<<<(N_NODESC + 7) / 8, 256>>>();

    // h = relu(agg1 @ W1 + b1) ; y2 = h @ W2   (fp16 tensor cores)
    {
        dim3 g1(D1C / 128, (N_NODESC + 127) / 128);
        gemm1_k<<<g1, 256>>>(b1);
        dim3 g2(D2C / 64, (N_NODESC + 127) / 128);
        gemm2_k<<<g2, 256>>>();
    }

    // Layer 2 aggregation at 64 channels (fp16 gather) + fused epilogue + re-zero
    n2h2_k<<<(N_HEDGESC + 15) / 16, 256>>>();
    h2n2_k<<<(N_NODESC + 15) / 16, 256>>>(b2, out);
}

// round 11
// speedup vs baseline: 1.4999x; 1.0220x over previous
#include <cuda_runtime.h>
#include <cuda_fp16.h>
#include <cstdint>
#include <cstddef>

// Problem constants (fixed shapes for Hgnn_17394617548829)
#define N_NODESC 50000
#define N_HEDGESC 5000
#define NNZC 800000
#define IN_C 128
#define D1C 256
#define D2C 64

// Scan chunking: 256 elements per block
#define NBLK_H 20    // ceil(5000/256)
#define NBLK_N 196   // ceil(50000/256)
#define NBLK   216

// ---------------------------------------------------------------------------
// Scratch (static device globals; no allocation anywhere).
// INVARIANT: g_deg / g_cnt are all-zero at kernel_launch entry.
//   - first run: .bss zero-initialization
//   - later runs: zeroed at the tail of h2n2_k (last kernel of previous run)
// ---------------------------------------------------------------------------
__device__ __half g_xh  [(size_t)N_NODESC * IN_C];   // 12.8 MB (x in fp16)
__device__ __half g_e1h [(size_t)N_HEDGESC * IN_C];  // 1.28 MB
__device__ __half g_a1h [(size_t)N_NODESC * IN_C];   // 12.8 MB (agg1 fp16)
__device__ __half g_hh  [(size_t)N_NODESC * D1C];    // 25.6 MB
__device__ __half g_y2h [(size_t)N_NODESC * D2C];    // 6.4 MB
__device__ __half g_e2h [(size_t)N_HEDGESC * D2C];   // 0.64 MB
__device__ __half g_w1h [(size_t)D1C * IN_C];        // W1^T [N=256][K=128]
__device__ __half g_w2h [(size_t)D2C * D1C];         // W2^T [N=64][K=256]
__device__ int   g_cnt [N_HEDGESC];
__device__ int   g_deg [N_NODESC];
__device__ int   g_hoff[N_HEDGESC + 1];
__device__ int   g_noff[N_NODESC + 1];
__device__ int   g_hcur[N_HEDGESC];
__device__ int   g_ncur[N_NODESC];
__device__ unsigned short g_hlist[NNZC];             // node ids (fit in u16)
__device__ unsigned short g_nlist[NNZC];             // hedge ids (fit in u16)
__device__ float g_dinv[N_NODESC];
__device__ float g_binv[N_HEDGESC];
__device__ int   g_part[NBLK];
__device__ int   g_partoff[NBLK];
__device__ int   g_bar0;            // grid-barrier counters (reset in cvt_k)
__device__ int   g_bar1;

// ---------------------------------------------------------------------------
// fp16 helpers
// ---------------------------------------------------------------------------
__device__ __forceinline__ void acc_h2(float4& a, uint2 u) {
    __half2 p0 = *reinterpret_cast<__half2*>(&u.x);
    __half2 p1 = *reinterpret_cast<__half2*>(&u.y);
    float2 f0 = __half22float2(p0);
    float2 f1 = __half22float2(p1);
    a.x += f0.x; a.y += f0.y; a.z += f1.x; a.w += f1.y;
}

__device__ __forceinline__ uint2 pack_h2(float x, float y, float z, float w) {
    __half2 h0 = __floats2half2_rn(x, y);
    __half2 h1 = __floats2half2_rn(z, w);
    uint2 u;
    u.x = *reinterpret_cast<unsigned*>(&h0);
    u.y = *reinterpret_cast<unsigned*>(&h1);
    return u;
}

// ---------------------------------------------------------------------------
// 0. FUSED: degree histograms (fire-and-forget REDs, counters pre-zeroed) +
//    fp16 conversions + grid-barrier reset.
// ---------------------------------------------------------------------------
__global__ void __launch_bounds__(256) cvt_k(const float* __restrict__ x,
                                             const float* __restrict__ W1,
                                             const float* __restrict__ W2,
                                             const int* __restrict__ ni,
                                             const int* __restrict__ hi) {
    int i = blockIdx.x * blockDim.x + threadIdx.x;
    int stride = gridDim.x * blockDim.x;
    if (i == 0) { g_bar0 = 0; g_bar1 = 0; }

    for (int j = i; j < NNZC / 2; j += stride) {
        int2 nn = *reinterpret_cast<const int2*>(ni + 2 * j);
        int2 hh = *reinterpret_cast<const int2*>(hi + 2 * j);
        atomicAdd(&g_deg[nn.x], 1);
        atomicAdd(&g_deg[nn.y], 1);
        atomicAdd(&g_cnt[hh.x], 1);
        atomicAdd(&g_cnt[hh.y], 1);
    }

    const float4* x4 = reinterpret_cast<const float4*>(x);
    uint2* xh2 = reinterpret_cast<uint2*>(g_xh);
    for (int j = i; j < N_NODESC * IN_C / 4; j += stride) {
        float4 v = x4[j];
        xh2[j] = pack_h2(v.x, v.y, v.z, v.w);
    }
    for (int j = i; j < D1C * IN_C; j += stride) {
        int n = j / IN_C, k = j % IN_C;
        g_w1h[j] = __float2half(W1[(size_t)k * D1C + n]);
    }
    for (int j = i; j < D2C * D1C; j += stride) {
        int n = j / D1C, k = j % D1C;
        g_w2h[j] = __float2half(W2[(size_t)k * D2C + n]);
    }
}

// ---------------------------------------------------------------------------
// 1. fused segmented exclusive scan (one kernel, grid barrier; phase 2 in
//    block-0 shared memory). 216 blocks <= 1 wave -> no deadlock.
// ---------------------------------------------------------------------------
__global__ void __launch_bounds__(256) scan_k() {
    __shared__ int sh[256];
    __shared__ int shp[NBLK];
    const int b   = blockIdx.x;
    const int tid = threadIdx.x;
    const int* src; int* off; int* cur; float* inv;
    int idx, n;
    if (b < NBLK_H) {
        src = g_cnt; off = g_hoff; cur = g_hcur; inv = g_binv;
        idx = b * 256 + tid; n = N_HEDGESC;
    } else {
        src = g_deg; off = g_noff; cur = g_ncur; inv = g_dinv;
        idx = (b - NBLK_H) * 256 + tid; n = N_NODESC;
    }
    int v = (idx < n) ? src[idx] : 0;

    sh[tid] = v;
    __syncthreads();
    for (int d = 1; d < 256; d <<= 1) {
        int t = (tid >= d) ? sh[tid - d] : 0;
        __syncthreads();
        sh[tid] += t;
        __syncthreads();
    }
    int incl = sh[tid];
    if (tid == 255) {
        g_part[b] = incl;
        __threadfence();
        atomicAdd(&g_bar0, 1);
    }

    if (b == 0) {
        if (tid == 0) {
            while (atomicAdd(&g_bar0, 0) < NBLK) __nanosleep(32);
        }
        __syncthreads();
        __threadfence();
        if (tid < NBLK) shp[tid] = g_part[tid];
        __syncthreads();
        if (tid == 0) {
            int run = 0;
            for (int i = 0; i < NBLK_H; i++) { int c = shp[i]; shp[i] = run; run += c; }
            run = 0;
            for (int i = NBLK_H; i < NBLK; i++) { int c = shp[i]; shp[i] = run; run += c; }
        }
        __syncthreads();
        if (tid < NBLK) g_partoff[tid] = shp[tid];
        __threadfence();
        __syncthreads();
        if (tid == 0) atomicExch(&g_bar1, 1);
    }
    if (tid == 0) {
        while (atomicAdd(&g_bar1, 0) == 0) __nanosleep(32);
    }
    __syncthreads();
    __threadfence();

    if (idx < n) {
        int excl = incl - v + g_partoff[b];
        off[idx] = excl;
        cur[idx] = excl;
        inv[idx] = (v > 0) ? 1.0f / (float)v : 0.0f;
    }
    if (b == 0 && tid == 0) {
        g_hoff[N_HEDGESC] = NNZC;
        g_noff[N_NODESC]  = NNZC;
    }
}

// ---------------------------------------------------------------------------
// 2. scatter edges into both CSR member lists (2 edges/thread, u16 payloads)
// ---------------------------------------------------------------------------
__global__ void __launch_bounds__(256) build_k(const int* __restrict__ ni,
                                               const int* __restrict__ hi) {
    int i = blockIdx.x * blockDim.x + threadIdx.x;
    if (2 * i >= NNZC) return;
    int2 nn = *reinterpret_cast<const int2*>(ni + 2 * i);
    int2 hh = *reinterpret_cast<const int2*>(hi + 2 * i);
    int p0 = atomicAdd(&g_hcur[hh.x], 1);
    int p1 = atomicAdd(&g_hcur[hh.y], 1);
    int q0 = atomicAdd(&g_ncur[nn.x], 1);
    int q1 = atomicAdd(&g_ncur[nn.y], 1);
    g_hlist[p0] = (unsigned short)nn.x;
    g_hlist[p1] = (unsigned short)nn.y;
    g_nlist[q0] = (unsigned short)hh.x;
    g_nlist[q1] = (unsigned short)hh.y;
}

// ---------------------------------------------------------------------------
// Gather kernels. fp16 payload, fp32 accumulation, packed u16 index loads.
// Hedge-side (long segments, few of them): 2 warps/groups per segment with
// smem combine — doubles warp parallelism.
// ---------------------------------------------------------------------------

// e1h[h] = binv[h] * sum x_h[n]   (128 ch; 2 warps per hedge)
__global__ void __launch_bounds__(256) n2h1_k() {
    __shared__ float sm[4][IN_C];
    const int hloc = threadIdx.x >> 6;         // 0..3 (64 threads per hedge)
    const int half = (threadIdx.x >> 5) & 1;   // warp within the pair
    const int lane = threadIdx.x & 31;
    const int h = blockIdx.x * 4 + hloc;       // grid exact: 5000/4 = 1250
    const int s = g_hoff[h], e = g_hoff[h + 1];
    const int mid = (s + e) >> 1;
    int j   = half ? mid : s;
    int end = half ? e   : mid;

    float4 a0 = make_float4(0.f, 0.f, 0.f, 0.f);
    float4 a1 = make_float4(0.f, 0.f, 0.f, 0.f);
    // align to 4 for packed index loads
    for (; j < end && (j & 3); j++) {
        int n0 = __ldg(g_hlist + j);
        uint2 u0 = __ldg(reinterpret_cast<const uint2*>(g_xh + (size_t)n0 * IN_C) + lane);
        acc_h2(a0, u0);
    }
    for (; j + 4 <= end; j += 4) {
        uint2 idx = __ldg(reinterpret_cast<const uint2*>(g_hlist + j));
        int n0 = idx.x & 0xFFFF, n1 = idx.x >> 16;
        int n2 = idx.y & 0xFFFF, n3 = idx.y >> 16;
        uint2 u0 = __ldg(reinterpret_cast<const uint2*>(g_xh + (size_t)n0 * IN_C) + lane);
        uint2 u1 = __ldg(reinterpret_cast<const uint2*>(g_xh + (size_t)n1 * IN_C) + lane);
        uint2 u2 = __ldg(reinterpret_cast<const uint2*>(g_xh + (size_t)n2 * IN_C) + lane);
        uint2 u3 = __ldg(reinterpret_cast<const uint2*>(g_xh + (size_t)n3 * IN_C) + lane);
        acc_h2(a0, u0); acc_h2(a1, u1); acc_h2(a0, u2); acc_h2(a1, u3);
    }
    for (; j < end; j++) {
        int n0 = __ldg(g_hlist + j);
        uint2 u0 = __ldg(reinterpret_cast<const uint2*>(g_xh + (size_t)n0 * IN_C) + lane);
        acc_h2(a0, u0);
    }
    float4 t;
    t.x = a0.x + a1.x; t.y = a0.y + a1.y; t.z = a0.z + a1.z; t.w = a0.w + a1.w;
    if (half == 1)
        *reinterpret_cast<float4*>(&sm[hloc][lane * 4]) = t;
    __syncthreads();
    if (half == 0) {
        float4 o = *reinterpret_cast<const float4*>(&sm[hloc][lane * 4]);
        float bi = g_binv[h];
        reinterpret_cast<uint2*>(g_e1h + (size_t)h * IN_C)[lane] =
            pack_h2((t.x + o.x) * bi, (t.y + o.y) * bi,
                    (t.z + o.z) * bi, (t.w + o.w) * bi);
    }
}

// a1h[n] = dinv[n] * sum e1h[h]   (128 ch, warp per node; packed idx loads)
__global__ void __launch_bounds__(256) h2n1_k() {
    int w = blockIdx.x * 8 + (threadIdx.x >> 5);
    if (w >= N_NODESC) return;
    int lane = threadIdx.x & 31;
    int j = g_noff[w], end = g_noff[w + 1];
    float4 a0 = make_float4(0.f, 0.f, 0.f, 0.f);
    float4 a1 = make_float4(0.f, 0.f, 0.f, 0.f);
    for (; j < end && (j & 3); j++) {
        int h0 = __ldg(g_nlist + j);
        uint2 u0 = __ldg(reinterpret_cast<const uint2*>(g_e1h + (size_t)h0 * IN_C) + lane);
        acc_h2(a0, u0);
    }
    for (; j + 4 <= end; j += 4) {
        uint2 idx = __ldg(reinterpret_cast<const uint2*>(g_nlist + j));
        int h0 = idx.x & 0xFFFF, h1 = idx.x >> 16;
        int h2 = idx.y & 0xFFFF, h3 = idx.y >> 16;
        uint2 u0 = __ldg(reinterpret_cast<const uint2*>(g_e1h + (size_t)h0 * IN_C) + lane);
        uint2 u1 = __ldg(reinterpret_cast<const uint2*>(g_e1h + (size_t)h1 * IN_C) + lane);
        uint2 u2 = __ldg(reinterpret_cast<const uint2*>(g_e1h + (size_t)h2 * IN_C) + lane);
        uint2 u3 = __ldg(reinterpret_cast<const uint2*>(g_e1h + (size_t)h3 * IN_C) + lane);
        acc_h2(a0, u0); acc_h2(a1, u1); acc_h2(a0, u2); acc_h2(a1, u3);
    }
    for (; j < end; j++) {
        int h0 = __ldg(g_nlist + j);
        uint2 u0 = __ldg(reinterpret_cast<const uint2*>(g_e1h + (size_t)h0 * IN_C) + lane);
        acc_h2(a0, u0);
    }
    float di = g_dinv[w];
    reinterpret_cast<uint2*>(g_a1h + (size_t)w * IN_C)[lane] =
        pack_h2((a0.x + a1.x) * di, (a0.y + a1.y) * di,
                (a0.z + a1.z) * di, (a0.w + a1.w) * di);
}

// e2h[h] = binv[h] * sum y2h[n]   (64 ch; 2 x 16-lane groups per hedge)
__global__ void __launch_bounds__(256) n2h2_k() {
    __shared__ float sm[8][D2C];
    const int hloc = threadIdx.x >> 5;         // 0..7 (32 threads per hedge)
    const int half = (threadIdx.x >> 4) & 1;   // 16-lane group within the pair
    const int lane = threadIdx.x & 15;
    const int h = blockIdx.x * 8 + hloc;       // grid exact: 5000/8 = 625
    const int s = g_hoff[h], e = g_hoff[h + 1];
    const int mid = (s + e) >> 1;
    int j   = half ? mid : s;
    int end = half ? e   : mid;

    float4 a0 = make_float4(0.f, 0.f, 0.f, 0.f);
    float4 a1 = make_float4(0.f, 0.f, 0.f, 0.f);
    for (; j < end && (j & 3); j++) {
        int n0 = __ldg(g_hlist + j);
        uint2 u0 = __ldg(reinterpret_cast<const uint2*>(g_y2h + (size_t)n0 * D2C) + lane);
        acc_h2(a0, u0);
    }
    for (; j + 4 <= end; j += 4) {
        uint2 idx = __ldg(reinterpret_cast<const uint2*>(g_hlist + j));
        int n0 = idx.x & 0xFFFF, n1 = idx.x >> 16;
        int n2 = idx.y & 0xFFFF, n3 = idx.y >> 16;
        uint2 u0 = __ldg(reinterpret_cast<const uint2*>(g_y2h + (size_t)n0 * D2C) + lane);
        uint2 u1 = __ldg(reinterpret_cast<const uint2*>(g_y2h + (size_t)n1 * D2C) + lane);
        uint2 u2 = __ldg(reinterpret_cast<const uint2*>(g_y2h + (size_t)n2 * D2C) + lane);
        uint2 u3 = __ldg(reinterpret_cast<const uint2*>(g_y2h + (size_t)n3 * D2C) + lane);
        acc_h2(a0, u0); acc_h2(a1, u1); acc_h2(a0, u2); acc_h2(a1, u3);
    }
    for (; j < end; j++) {
        int n0 = __ldg(g_hlist + j);
        uint2 u0 = __ldg(reinterpret_cast<const uint2*>(g_y2h + (size_t)n0 * D2C) + lane);
        acc_h2(a0, u0);
    }
    float4 t;
    t.x = a0.x + a1.x; t.y = a0.y + a1.y; t.z = a0.z + a1.z; t.w = a0.w + a1.w;
    if (half == 1)
        *reinterpret_cast<float4*>(&sm[hloc][lane * 4]) = t;
    __syncthreads();
    if (half == 0) {
        float4 o = *reinterpret_cast<const float4*>(&sm[hloc][lane * 4]);
        float bi = g_binv[h];
        reinterpret_cast<uint2*>(g_e2h + (size_t)h * D2C)[lane] =
            pack_h2((t.x + o.x) * bi, (t.y + o.y) * bi,
                    (t.z + o.z) * bi, (t.w + o.w) * bi);
    }
}

// out[n] = relu(dinv[n] * sum e2h[h] + b2); tail restores zero-counter invariant
__global__ void __launch_bounds__(256) h2n2_k(const float* __restrict__ b2,
                                              float* __restrict__ out) {
    int g = blockIdx.x * 16 + (threadIdx.x >> 4);
    if (g < N_NODESC) {
        int lane = threadIdx.x & 15;
        int j = g_noff[g], end = g_noff[g + 1];
        float4 a0 = make_float4(0.f, 0.f, 0.f, 0.f);
        float4 a1 = make_float4(0.f, 0.f, 0.f, 0.f);
        for (; j < end && (j & 3); j++) {
            int h0 = __ldg(g_nlist + j);
            uint2 u0 = __ldg(reinterpret_cast<const uint2*>(g_e2h + (size_t)h0 * D2C) + lane);
            acc_h2(a0, u0);
        }
        for (; j + 4 <= end; j += 4) {
            uint2 idx = __ldg(reinterpret_cast<const uint2*>(g_nlist + j));
            int h0 = idx.x & 0xFFFF, h1 = idx.x >> 16;
            int h2 = idx.y & 0xFFFF, h3 = idx.y >> 16;
            uint2 u0 = __ldg(reinterpret_cast<const uint2*>(g_e2h + (size_t)h0 * D2C) + lane);
            uint2 u1 = __ldg(reinterpret_cast<const uint2*>(g_e2h + (size_t)h1 * D2C) + lane);
            uint2 u2 = __ldg(reinterpret_cast<const uint2*>(g_e2h + (size_t)h2 * D2C) + lane);
            uint2 u3 = __ldg(reinterpret_cast<const uint2*>(g_e2h + (size_t)h3 * D2C) + lane);
            acc_h2(a0, u0); acc_h2(a1, u1); acc_h2(a0, u2); acc_h2(a1, u3);
        }
        for (; j < end; j++) {
            int h0 = __ldg(g_nlist + j);
            uint2 u0 = __ldg(reinterpret_cast<const uint2*>(g_e2h + (size_t)h0 * D2C) + lane);
            acc_h2(a0, u0);
        }
        float di = g_dinv[g];
        float4 b = __ldg(reinterpret_cast<const float4*>(b2) + lane);
        float4 r;
        r.x = fmaxf(fmaf(a0.x + a1.x, di, b.x), 0.f);
        r.y = fmaxf(fmaf(a0.y + a1.y, di, b.y), 0.f);
        r.z = fmaxf(fmaf(a0.z + a1.z, di, b.z), 0.f);
        r.w = fmaxf(fmaf(a0.w + a1.w, di, b.w), 0.f);
        reinterpret_cast<float4*>(out + (size_t)g * D2C)[lane] = r;
    }
    // restore invariant: counters zero for next launch
    int t = blockIdx.x * blockDim.x + threadIdx.x;
    int stride = gridDim.x * blockDim.x;
    for (int j = t; j < N_NODESC; j += stride) g_deg[j] = 0;
    for (int j = t; j < N_HEDGESC; j += stride) g_cnt[j] = 0;
}

// ---------------------------------------------------------------------------
// fp16 tensor-core GEMM (R6 verified).
// ---------------------------------------------------------------------------
__device__ __forceinline__ void mma_f16(float& d0, float& d1, float& d2, float& d3,
                                        uint32_t a0, uint32_t a1, uint32_t a2, uint32_t a3,
                                        uint32_t b0, uint32_t b1) {
    asm volatile(
        "mma.sync.aligned.m16n8k16.row.col.f32.f16.f16.f32 "
        "{%0,%1,%2,%3}, {%4,%5,%6,%7}, {%8,%9}, {%0,%1,%2,%3};"
        : "+f"(d0), "+f"(d1), "+f"(d2), "+f"(d3)
        : "r"(a0), "r"(a1), "r"(a2), "r"(a3), "r"(b0), "r"(b1));
}

template <int BM, int BN, int BK, int WARPS_M, int WARPS_N, bool EPI>
__device__ __forceinline__ void gemm_f16_body(const __half* __restrict__ A,
                                              const __half* __restrict__ Bt,
                                              const float* __restrict__ bias,
                                              __half* __restrict__ C,
                                              int M, int N, int K) {
    constexpr int THREADS = WARPS_M * WARPS_N * 32;
    constexpr int WM = BM / WARPS_M;
    constexpr int WN = BN / WARPS_N;
    constexpr int MI = WM / 16;
    constexpr int NI = WN / 8;
    constexpr int PAD = 8;
    constexpr int AV = (BM * BK / 8) / THREADS;
    constexpr int BV = (BN * BK / 8) / THREADS;

    __shared__ __align__(16) __half As[BM][BK + PAD];
    __shared__ __align__(16) __half Bs[BN][BK + PAD];

    const int tid  = threadIdx.x;
    const int warp = tid >> 5;
    const int lane = tid & 31;
    const int wm   = warp / WARPS_N;
    const int wn   = warp % WARPS_N;
    const int row0 = blockIdx.y * BM;
    const int col0 = blockIdx.x * BN;
    const int lq   = lane >> 2;
    const int lr   = lane & 3;

    float acc[MI][NI][4];
#pragma unroll
    for (int i = 0; i < MI; i++)
#pragma unroll
        for (int j = 0; j < NI; j++)
#pragma unroll
            for (int c = 0; c < 4; c++) acc[i][j][c] = 0.f;

    for (int kt = 0; kt < K; kt += BK) {
#pragma unroll
        for (int i = 0; i < AV; i++) {
            int idx = tid + i * THREADS;
            int m   = idx / (BK / 8);
            int kc  = (idx % (BK / 8)) * 8;
            int grow = row0 + m;
            uint4 v = make_uint4(0, 0, 0, 0);
            if (grow < M)
                v = __ldg(reinterpret_cast<const uint4*>(A + (size_t)grow * K + kt + kc));
            *reinterpret_cast<uint4*>(&As[m][kc]) = v;
        }
#pragma unroll
        for (int i = 0; i < BV; i++) {
            int idx = tid + i * THREADS;
            int n   = idx / (BK / 8);
            int kc  = (idx % (BK / 8)) * 8;
            uint4 v = __ldg(reinterpret_cast<const uint4*>(Bt + (size_t)(col0 + n) * K + kt + kc));
            *reinterpret_cast<uint4*>(&Bs[n][kc]) = v;
        }
        __syncthreads();

#pragma unroll
        for (int ks = 0; ks < BK; ks += 16) {
            uint32_t af[MI][4];
            uint32_t bf[NI][2];
#pragma unroll
            for (int i = 0; i < MI; i++) {
                int m0 = wm * WM + i * 16;
                af[i][0] = *reinterpret_cast<const uint32_t*>(&As[m0 + lq    ][ks + 2 * lr    ]);
                af[i][1] = *reinterpret_cast<const uint32_t*>(&As[m0 + lq + 8][ks + 2 * lr    ]);
                af[i][2] = *reinterpret_cast<const uint32_t*>(&As[m0 + lq    ][ks + 2 * lr + 8]);
                af[i][3] = *reinterpret_cast<const uint32_t*>(&As[m0 + lq + 8][ks + 2 * lr + 8]);
            }
#pragma unroll
            for (int j = 0; j < NI; j++) {
                int n0 = wn * WN + j * 8;
                bf[j][0] = *reinterpret_cast<const uint32_t*>(&Bs[n0 + lq][ks + 2 * lr    ]);
                bf[j][1] = *reinterpret_cast<const uint32_t*>(&Bs[n0 + lq][ks + 2 * lr + 8]);
            }
#pragma unroll
            for (int i = 0; i < MI; i++)
#pragma unroll
                for (int j = 0; j < NI; j++)
                    mma_f16(acc[i][j][0], acc[i][j][1], acc[i][j][2], acc[i][j][3],
                            af[i][0], af[i][1], af[i][2], af[i][3],
                            bf[j][0], bf[j][1]);
        }
        __syncthreads();
    }

#pragma unroll
    for (int i = 0; i < MI; i++) {
#pragma unroll
        for (int j = 0; j < NI; j++) {
            int row = row0 + wm * WM + i * 16 + lq;
            int col = col0 + wn * WN + j * 8 + 2 * lr;
            float2 v0 = make_float2(acc[i][j][0], acc[i][j][1]);
            float2 v1 = make_float2(acc[i][j][2], acc[i][j][3]);
            if (EPI) {
                float b0 = bias[col], b1 = bias[col + 1];
                v0.x = fmaxf(v0.x + b0, 0.f);
                v0.y = fmaxf(v0.y + b1, 0.f);
                v1.x = fmaxf(v1.x + b0, 0.f);
                v1.y = fmaxf(v1.y + b1, 0.f);
            }
            if (row < M)
                *reinterpret_cast<__half2*>(&C[(size_t)row * N + col]) =
                    __floats2half2_rn(v0.x, v0.y);
            if (row + 8 < M)
                *reinterpret_cast<__half2*>(&C[(size_t)(row + 8) * N + col]) =
                    __floats2half2_rn(v1.x, v1.y);
        }
    }
}

// GEMM1: g_hh = relu(g_a1h @ W1 + b1)   [50000x128]@[128x256]
__global__ void __launch_bounds__(256) gemm1_k(const float* __restrict__ b1) {
    gemm_f16_body<128, 128, 32, 2, 4, true>(g_a1h, g_w1h, b1, g_hh, N_NODESC, D1C, IN_C);
}

// GEMM2: g_y2h = g_hh @ W2   [50000x256]@[256x64]
__global__ void __launch_bounds__(256) gemm2_k() {
    gemm_f16_body<128, 64, 32, 4, 2, false>(g_hh, g_w2h, nullptr, g_y2h, N_NODESC, D2C, D1C);
}

// ---------------------------------------------------------------------------
// Launch (9 kernels)
// ---------------------------------------------------------------------------
extern "C" void kernel_launch(void* const* d_in, const int* in_sizes, int n_in,
                              void* d_out, int out_size) {
    const float* x    = (const float*)d_in[0];
    const int*   edge = (const int*)d_in[1];
    const float* W1   = (const float*)d_in[2];
    const float* b1   = (const float*)d_in[3];
    const float* W2   = (const float*)d_in[4];
    const float* b2   = (const float*)d_in[5];
    float*       out  = (float*)d_out;

    const int* ni = edge;          // edge[0] = node_idx
    const int* hi = edge + NNZC;   // edge[1] = hedge_idx

    // fused hist + conversions + barrier reset; then scan + scatter
    cvt_k<<<1024, 256>>>(x, W1, W2, ni, hi);
    scan_k<<<NBLK, 256>>>();
    build_k<<<(NNZC / 2 + 255) / 256, 256>>>(ni, hi);

    // Layer 1 aggregation at 128 channels (split hedge-side gather)
    n2h1_k<<<N_HEDGESC / 4, 256>>>();
    h2n1_k<<<(N_NODESC + 7) / 8, 256>>>();

    // h = relu(agg1 @ W1 + b1) ; y2 = h @ W2   (fp16 tensor cores)
    {
        dim3 g1(D1C / 128, (N_NODESC + 127) / 128);
        gemm1_k<<<g1, 256>>>(b1);
        dim3 g2(D2C / 64, (N_NODESC + 127) / 128);
        gemm2_k<<<g2, 256>>>();
    }

    // Layer 2 aggregation at 64 channels (split hedge-side gather) + epilogue
    n2h2_k<<<N_HEDGESC / 8, 256>>>();
    h2n2_k<<<(N_NODESC + 15) / 16, 256>>>(b2, out);
}

// round 12
// speedup vs baseline: 1.5700x; 1.0468x over previous
#include <cuda_runtime.h>
#include <cuda_fp16.h>
#include <cstdint>
#include <cstddef>

// Problem constants (fixed shapes for Hgnn_17394617548829)
#define N_NODESC 50000
#define N_HEDGESC 5000
#define NNZC 800000
#define IN_C 128
#define D1C 256
#define D2C 64

// Scan chunking: 256 elements per block
#define NBLK_H 20    // ceil(5000/256)
#define NBLK_N 196   // ceil(50000/256)
#define NBLK   216

// ---------------------------------------------------------------------------
// Scratch (static device globals; no allocation anywhere).
// INVARIANT: g_deg / g_cnt are all-zero at kernel_launch entry.
// ---------------------------------------------------------------------------
__device__ __half g_xh  [(size_t)N_NODESC * IN_C];   // 12.8 MB (x in fp16)
__device__ __half g_e1h [(size_t)N_HEDGESC * IN_C];  // 1.28 MB
__device__ __half g_a1h [(size_t)N_NODESC * IN_C];   // 12.8 MB (agg1 fp16)
__device__ __half g_hh  [(size_t)N_NODESC * D1C];    // 25.6 MB
__device__ __half g_y2h [(size_t)N_NODESC * D2C];    // 6.4 MB
__device__ __half g_e2h [(size_t)N_HEDGESC * D2C];   // 0.64 MB
__device__ __half g_w1h [(size_t)D1C * IN_C];        // W1^T [N=256][K=128]
__device__ __half g_w2h [(size_t)D2C * D1C];         // W2^T [N=64][K=256]
__device__ int   g_cnt [N_HEDGESC];
__device__ int   g_deg [N_NODESC];
__device__ int   g_hoff[N_HEDGESC + 1];
__device__ int   g_noff[N_NODESC + 1];
__device__ int   g_hcur[N_HEDGESC];
__device__ int   g_ncur[N_NODESC];
__device__ unsigned short g_hlist[NNZC];             // node ids (fit in u16)
__device__ unsigned short g_nlist[NNZC];             // hedge ids (fit in u16)
__device__ float g_dinv[N_NODESC];
__device__ float g_binv[N_HEDGESC];
__device__ int   g_part[NBLK];
__device__ int   g_partoff[NBLK];
__device__ int   g_bar0;            // grid-barrier counters (reset in cvt_k)
__device__ int   g_bar1;

// ---------------------------------------------------------------------------
// fp16 helpers
// ---------------------------------------------------------------------------
__device__ __forceinline__ void acc_h2(float4& a, uint2 u) {
    float2 f0 = __half22float2(*reinterpret_cast<__half2*>(&u.x));
    float2 f1 = __half22float2(*reinterpret_cast<__half2*>(&u.y));
    a.x += f0.x; a.y += f0.y; a.z += f1.x; a.w += f1.y;
}

// Pairwise fp16 combine (HADD2), then fp32 accumulate: 4+... ops vs 8+8.
__device__ __forceinline__ void acc_pair(float4& a, uint2 u0, uint2 u1) {
    __half2 sx = __hadd2(*reinterpret_cast<__half2*>(&u0.x),
                         *reinterpret_cast<__half2*>(&u1.x));
    __half2 sy = __hadd2(*reinterpret_cast<__half2*>(&u0.y),
                         *reinterpret_cast<__half2*>(&u1.y));
    float2 fx = __half22float2(sx);
    float2 fy = __half22float2(sy);
    a.x += fx.x; a.y += fx.y; a.z += fy.x; a.w += fy.y;
}

__device__ __forceinline__ uint2 pack_h2(float x, float y, float z, float w) {
    __half2 h0 = __floats2half2_rn(x, y);
    __half2 h1 = __floats2half2_rn(z, w);
    uint2 u;
    u.x = *reinterpret_cast<unsigned*>(&h0);
    u.y = *reinterpret_cast<unsigned*>(&h1);
    return u;
}

// ---------------------------------------------------------------------------
// 0. FUSED: degree histograms (fire-and-forget REDs) + fp16 conversions +
//    grid-barrier reset.
// ---------------------------------------------------------------------------
__global__ void __launch_bounds__(256) cvt_k(const float* __restrict__ x,
                                             const float* __restrict__ W1,
                                             const float* __restrict__ W2,
                                             const int* __restrict__ ni,
                                             const int* __restrict__ hi) {
    int i = blockIdx.x * blockDim.x + threadIdx.x;
    int stride = gridDim.x * blockDim.x;
    if (i == 0) { g_bar0 = 0; g_bar1 = 0; }

    for (int j = i; j < NNZC / 2; j += stride) {
        int2 nn = *reinterpret_cast<const int2*>(ni + 2 * j);
        int2 hh = *reinterpret_cast<const int2*>(hi + 2 * j);
        atomicAdd(&g_deg[nn.x], 1);
        atomicAdd(&g_deg[nn.y], 1);
        atomicAdd(&g_cnt[hh.x], 1);
        atomicAdd(&g_cnt[hh.y], 1);
    }

    const float4* x4 = reinterpret_cast<const float4*>(x);
    uint2* xh2 = reinterpret_cast<uint2*>(g_xh);
    for (int j = i; j < N_NODESC * IN_C / 4; j += stride) {
        float4 v = x4[j];
        xh2[j] = pack_h2(v.x, v.y, v.z, v.w);
    }
    for (int j = i; j < D1C * IN_C; j += stride) {
        int n = j / IN_C, k = j % IN_C;
        g_w1h[j] = __float2half(W1[(size_t)k * D1C + n]);
    }
    for (int j = i; j < D2C * D1C; j += stride) {
        int n = j / D1C, k = j % D1C;
        g_w2h[j] = __float2half(W2[(size_t)k * D2C + n]);
    }
}

// ---------------------------------------------------------------------------
// 1. fused segmented exclusive scan (one kernel, grid barrier; phase 2 in
//    block-0 shared memory). 216 blocks <= 1 wave -> no deadlock.
// ---------------------------------------------------------------------------
__global__ void __launch_bounds__(256) scan_k() {
    __shared__ int sh[256];
    __shared__ int shp[NBLK];
    const int b   = blockIdx.x;
    const int tid = threadIdx.x;
    const int* src; int* off; int* cur; float* inv;
    int idx, n;
    if (b < NBLK_H) {
        src = g_cnt; off = g_hoff; cur = g_hcur; inv = g_binv;
        idx = b * 256 + tid; n = N_HEDGESC;
    } else {
        src = g_deg; off = g_noff; cur = g_ncur; inv = g_dinv;
        idx = (b - NBLK_H) * 256 + tid; n = N_NODESC;
    }
    int v = (idx < n) ? src[idx] : 0;

    sh[tid] = v;
    __syncthreads();
    for (int d = 1; d < 256; d <<= 1) {
        int t = (tid >= d) ? sh[tid - d] : 0;
        __syncthreads();
        sh[tid] += t;
        __syncthreads();
    }
    int incl = sh[tid];
    if (tid == 255) {
        g_part[b] = incl;
        __threadfence();
        atomicAdd(&g_bar0, 1);
    }

    if (b == 0) {
        if (tid == 0) {
            while (atomicAdd(&g_bar0, 0) < NBLK) __nanosleep(32);
        }
        __syncthreads();
        __threadfence();
        if (tid < NBLK) shp[tid] = g_part[tid];
        __syncthreads();
        if (tid == 0) {
            int run = 0;
            for (int i = 0; i < NBLK_H; i++) { int c = shp[i]; shp[i] = run; run += c; }
            run = 0;
            for (int i = NBLK_H; i < NBLK; i++) { int c = shp[i]; shp[i] = run; run += c; }
        }
        __syncthreads();
        if (tid < NBLK) g_partoff[tid] = shp[tid];
        __threadfence();
        __syncthreads();
        if (tid == 0) atomicExch(&g_bar1, 1);
    }
    if (tid == 0) {
        while (atomicAdd(&g_bar1, 0) == 0) __nanosleep(32);
    }
    __syncthreads();
    __threadfence();

    if (idx < n) {
        int excl = incl - v + g_partoff[b];
        off[idx] = excl;
        cur[idx] = excl;
        inv[idx] = (v > 0) ? 1.0f / (float)v : 0.0f;
    }
    if (b == 0 && tid == 0) {
        g_hoff[N_HEDGESC] = NNZC;
        g_noff[N_NODESC]  = NNZC;
    }
}

// ---------------------------------------------------------------------------
// 2. scatter edges into both CSR member lists (2 edges/thread, u16 payloads)
// ---------------------------------------------------------------------------
__global__ void __launch_bounds__(256) build_k(const int* __restrict__ ni,
                                               const int* __restrict__ hi) {
    int i = blockIdx.x * blockDim.x + threadIdx.x;
    if (2 * i >= NNZC) return;
    int2 nn = *reinterpret_cast<const int2*>(ni + 2 * i);
    int2 hh = *reinterpret_cast<const int2*>(hi + 2 * i);
    int p0 = atomicAdd(&g_hcur[hh.x], 1);
    int p1 = atomicAdd(&g_hcur[hh.y], 1);
    int q0 = atomicAdd(&g_ncur[nn.x], 1);
    int q1 = atomicAdd(&g_ncur[nn.y], 1);
    g_hlist[p0] = (unsigned short)nn.x;
    g_hlist[p1] = (unsigned short)nn.y;
    g_nlist[q0] = (unsigned short)hh.x;
    g_nlist[q1] = (unsigned short)hh.y;
}

// ---------------------------------------------------------------------------
// Gather kernels. fp16 payload, pairwise HADD2 combine, fp32 accumulation,
// packed u16 index loads, 32-bit address math.
// ---------------------------------------------------------------------------

// e1h[h] = binv[h] * sum x_h[n]   (128 ch; 2 warps per hedge)
__global__ void __launch_bounds__(256) n2h1_k() {
    __shared__ float sm[4][IN_C];
    const int hloc = threadIdx.x >> 6;
    const int half = (threadIdx.x >> 5) & 1;
    const int lane = threadIdx.x & 31;
    const int h = blockIdx.x * 4 + hloc;       // grid exact: 5000/4 = 1250
    const int s = g_hoff[h], e = g_hoff[h + 1];
    const int mid = (s + e) >> 1;
    int j   = half ? mid : s;
    int end = half ? e   : mid;

    float4 a0 = make_float4(0.f, 0.f, 0.f, 0.f);
    float4 a1 = make_float4(0.f, 0.f, 0.f, 0.f);
    for (; j < end && (j & 3); j++) {
        int n0 = __ldg(g_hlist + j);
        uint2 u0 = __ldg(reinterpret_cast<const uint2*>(g_xh + n0 * IN_C) + lane);
        acc_h2(a0, u0);
    }
    for (; j + 4 <= end; j += 4) {
        uint2 idx = __ldg(reinterpret_cast<const uint2*>(g_hlist + j));
        int n0 = idx.x & 0xFFFF, n1 = idx.x >> 16;
        int n2 = idx.y & 0xFFFF, n3 = idx.y >> 16;
        uint2 u0 = __ldg(reinterpret_cast<const uint2*>(g_xh + n0 * IN_C) + lane);
        uint2 u1 = __ldg(reinterpret_cast<const uint2*>(g_xh + n1 * IN_C) + lane);
        uint2 u2 = __ldg(reinterpret_cast<const uint2*>(g_xh + n2 * IN_C) + lane);
        uint2 u3 = __ldg(reinterpret_cast<const uint2*>(g_xh + n3 * IN_C) + lane);
        acc_pair(a0, u0, u1);
        acc_pair(a1, u2, u3);
    }
    for (; j < end; j++) {
        int n0 = __ldg(g_hlist + j);
        uint2 u0 = __ldg(reinterpret_cast<const uint2*>(g_xh + n0 * IN_C) + lane);
        acc_h2(a0, u0);
    }
    float4 t;
    t.x = a0.x + a1.x; t.y = a0.y + a1.y; t.z = a0.z + a1.z; t.w = a0.w + a1.w;
    if (half == 1)
        *reinterpret_cast<float4*>(&sm[hloc][lane * 4]) = t;
    __syncthreads();
    if (half == 0) {
        float4 o = *reinterpret_cast<const float4*>(&sm[hloc][lane * 4]);
        float bi = g_binv[h];
        reinterpret_cast<uint2*>(g_e1h + h * IN_C)[lane] =
            pack_h2((t.x + o.x) * bi, (t.y + o.y) * bi,
                    (t.z + o.z) * bi, (t.w + o.w) * bi);
    }
}

// a1h[n] = dinv[n] * sum e1h[h]   (128 ch, warp per node)
__global__ void __launch_bounds__(256) h2n1_k() {
    int w = blockIdx.x * 8 + (threadIdx.x >> 5);
    if (w >= N_NODESC) return;
    int lane = threadIdx.x & 31;
    int j = g_noff[w], end = g_noff[w + 1];
    float4 a0 = make_float4(0.f, 0.f, 0.f, 0.f);
    float4 a1 = make_float4(0.f, 0.f, 0.f, 0.f);
    for (; j < end && (j & 3); j++) {
        int h0 = __ldg(g_nlist + j);
        uint2 u0 = __ldg(reinterpret_cast<const uint2*>(g_e1h + h0 * IN_C) + lane);
        acc_h2(a0, u0);
    }
    for (; j + 4 <= end; j += 4) {
        uint2 idx = __ldg(reinterpret_cast<const uint2*>(g_nlist + j));
        int h0 = idx.x & 0xFFFF, h1 = idx.x >> 16;
        int h2 = idx.y & 0xFFFF, h3 = idx.y >> 16;
        uint2 u0 = __ldg(reinterpret_cast<const uint2*>(g_e1h + h0 * IN_C) + lane);
        uint2 u1 = __ldg(reinterpret_cast<const uint2*>(g_e1h + h1 * IN_C) + lane);
        uint2 u2 = __ldg(reinterpret_cast<const uint2*>(g_e1h + h2 * IN_C) + lane);
        uint2 u3 = __ldg(reinterpret_cast<const uint2*>(g_e1h + h3 * IN_C) + lane);
        acc_pair(a0, u0, u1);
        acc_pair(a1, u2, u3);
    }
    for (; j < end; j++) {
        int h0 = __ldg(g_nlist + j);
        uint2 u0 = __ldg(reinterpret_cast<const uint2*>(g_e1h + h0 * IN_C) + lane);
        acc_h2(a0, u0);
    }
    float di = g_dinv[w];
    reinterpret_cast<uint2*>(g_a1h + w * IN_C)[lane] =
        pack_h2((a0.x + a1.x) * di, (a0.y + a1.y) * di,
                (a0.z + a1.z) * di, (a0.w + a1.w) * di);
}

// e2h[h] = binv[h] * sum y2h[n]   (64 ch; 2 x 16-lane groups per hedge)
__global__ void __launch_bounds__(256) n2h2_k() {
    __shared__ float sm[8][D2C];
    const int hloc = threadIdx.x >> 5;
    const int half = (threadIdx.x >> 4) & 1;
    const int lane = threadIdx.x & 15;
    const int h = blockIdx.x * 8 + hloc;       // grid exact: 5000/8 = 625
    const int s = g_hoff[h], e = g_hoff[h + 1];
    const int mid = (s + e) >> 1;
    int j   = half ? mid : s;
    int end = half ? e   : mid;

    float4 a0 = make_float4(0.f, 0.f, 0.f, 0.f);
    float4 a1 = make_float4(0.f, 0.f, 0.f, 0.f);
    for (; j < end && (j & 3); j++) {
        int n0 = __ldg(g_hlist + j);
        uint2 u0 = __ldg(reinterpret_cast<const uint2*>(g_y2h + n0 * D2C) + lane);
        acc_h2(a0, u0);
    }
    for (; j + 4 <= end; j += 4) {
        uint2 idx = __ldg(reinterpret_cast<const uint2*>(g_hlist + j));
        int n0 = idx.x & 0xFFFF, n1 = idx.x >> 16;
        int n2 = idx.y & 0xFFFF, n3 = idx.y >> 16;
        uint2 u0 = __ldg(reinterpret_cast<const uint2*>(g_y2h + n0 * D2C) + lane);
        uint2 u1 = __ldg(reinterpret_cast<const uint2*>(g_y2h + n1 * D2C) + lane);
        uint2 u2 = __ldg(reinterpret_cast<const uint2*>(g_y2h + n2 * D2C) + lane);
        uint2 u3 = __ldg(reinterpret_cast<const uint2*>(g_y2h + n3 * D2C) + lane);
        acc_pair(a0, u0, u1);
        acc_pair(a1, u2, u3);
    }
    for (; j < end; j++) {
        int n0 = __ldg(g_hlist + j);
        uint2 u0 = __ldg(reinterpret_cast<const uint2*>(g_y2h + n0 * D2C) + lane);
        acc_h2(a0, u0);
    }
    float4 t;
    t.x = a0.x + a1.x; t.y = a0.y + a1.y; t.z = a0.z + a1.z; t.w = a0.w + a1.w;
    if (half == 1)
        *reinterpret_cast<float4*>(&sm[hloc][lane * 4]) = t;
    __syncthreads();
    if (half == 0) {
        float4 o = *reinterpret_cast<const float4*>(&sm[hloc][lane * 4]);
        float bi = g_binv[h];
        reinterpret_cast<uint2*>(g_e2h + h * D2C)[lane] =
            pack_h2((t.x + o.x) * bi, (t.y + o.y) * bi,
                    (t.z + o.z) * bi, (t.w + o.w) * bi);
    }
}

// out[n] = relu(dinv[n] * sum e2h[h] + b2); tail restores zero-counter invariant
__global__ void __launch_bounds__(256) h2n2_k(const float* __restrict__ b2,
                                              float* __restrict__ out) {
    int g = blockIdx.x * 16 + (threadIdx.x >> 4);
    if (g < N_NODESC) {
        int lane = threadIdx.x & 15;
        int j = g_noff[g], end = g_noff[g + 1];
        float4 a0 = make_float4(0.f, 0.f, 0.f, 0.f);
        float4 a1 = make_float4(0.f, 0.f, 0.f, 0.f);
        for (; j < end && (j & 3); j++) {
            int h0 = __ldg(g_nlist + j);
            uint2 u0 = __ldg(reinterpret_cast<const uint2*>(g_e2h + h0 * D2C) + lane);
            acc_h2(a0, u0);
        }
        for (; j + 4 <= end; j += 4) {
            uint2 idx = __ldg(reinterpret_cast<const uint2*>(g_nlist + j));
            int h0 = idx.x & 0xFFFF, h1 = idx.x >> 16;
            int h2 = idx.y & 0xFFFF, h3 = idx.y >> 16;
            uint2 u0 = __ldg(reinterpret_cast<const uint2*>(g_e2h + h0 * D2C) + lane);
            uint2 u1 = __ldg(reinterpret_cast<const uint2*>(g_e2h + h1 * D2C) + lane);
            uint2 u2 = __ldg(reinterpret_cast<const uint2*>(g_e2h + h2 * D2C) + lane);
            uint2 u3 = __ldg(reinterpret_cast<const uint2*>(g_e2h + h3 * D2C) + lane);
            acc_pair(a0, u0, u1);
            acc_pair(a1, u2, u3);
        }
        for (; j < end; j++) {
            int h0 = __ldg(g_nlist + j);
            uint2 u0 = __ldg(reinterpret_cast<const uint2*>(g_e2h + h0 * D2C) + lane);
            acc_h2(a0, u0);
        }
        float di = g_dinv[g];
        float4 b = __ldg(reinterpret_cast<const float4*>(b2) + lane);
        float4 r;
        r.x = fmaxf(fmaf(a0.x + a1.x, di, b.x), 0.f);
        r.y = fmaxf(fmaf(a0.y + a1.y, di, b.y), 0.f);
        r.z = fmaxf(fmaf(a0.z + a1.z, di, b.z), 0.f);
        r.w = fmaxf(fmaf(a0.w + a1.w, di, b.w), 0.f);
        reinterpret_cast<float4*>(out + g * D2C)[lane] = r;
    }
    // restore invariant: counters zero for next launch
    int t = blockIdx.x * blockDim.x + threadIdx.x;
    int stride = gridDim.x * blockDim.x;
    for (int j = t; j < N_NODESC; j += stride) g_deg[j] = 0;
    for (int j = t; j < N_HEDGESC; j += stride) g_cnt[j] = 0;
}

// ---------------------------------------------------------------------------
// fp16 tensor-core GEMM (R6 verified).
// ---------------------------------------------------------------------------
__device__ __forceinline__ void mma_f16(float& d0, float& d1, float& d2, float& d3,
                                        uint32_t a0, uint32_t a1, uint32_t a2, uint32_t a3,
                                        uint32_t b0, uint32_t b1) {
    asm volatile(
        "mma.sync.aligned.m16n8k16.row.col.f32.f16.f16.f32 "
        "{%0,%1,%2,%3}, {%4,%5,%6,%7}, {%8,%9}, {%0,%1,%2,%3};"
        : "+f"(d0), "+f"(d1), "+f"(d2), "+f"(d3)
        : "r"(a0), "r"(a1), "r"(a2), "r"(a3), "r"(b0), "r"(b1));
}

template <int BM, int BN, int BK, int WARPS_M, int WARPS_N, bool EPI>
__device__ __forceinline__ void gemm_f16_body(const __half* __restrict__ A,
                                              const __half* __restrict__ Bt,
                                              const float* __restrict__ bias,
                                              __half* __restrict__ C,
                                              int M, int N, int K) {
    constexpr int THREADS = WARPS_M * WARPS_N * 32;
    constexpr int WM = BM / WARPS_M;
    constexpr int WN = BN / WARPS_N;
    constexpr int MI = WM / 16;
    constexpr int NI = WN / 8;
    constexpr int PAD = 8;
    constexpr int AV = (BM * BK / 8) / THREADS;
    constexpr int BV = (BN * BK / 8) / THREADS;

    __shared__ __align__(16) __half As[BM][BK + PAD];
    __shared__ __align__(16) __half Bs[BN][BK + PAD];

    const int tid  = threadIdx.x;
    const int warp = tid >> 5;
    const int lane = tid & 31;
    const int wm   = warp / WARPS_N;
    const int wn   = warp % WARPS_N;
    const int row0 = blockIdx.y * BM;
    const int col0 = blockIdx.x * BN;
    const int lq   = lane >> 2;
    const int lr   = lane & 3;

    float acc[MI][NI][4];
#pragma unroll
    for (int i = 0; i < MI; i++)
#pragma unroll
        for (int j = 0; j < NI; j++)
#pragma unroll
            for (int c = 0; c < 4; c++) acc[i][j][c] = 0.f;

    for (int kt = 0; kt < K; kt += BK) {
#pragma unroll
        for (int i = 0; i < AV; i++) {
            int idx = tid + i * THREADS;
            int m   = idx / (BK / 8);
            int kc  = (idx % (BK / 8)) * 8;
            int grow = row0 + m;
            uint4 v = make_uint4(0, 0, 0, 0);
            if (grow < M)
                v = __ldg(reinterpret_cast<const uint4*>(A + (size_t)grow * K + kt + kc));
            *reinterpret_cast<uint4*>(&As[m][kc]) = v;
        }
#pragma unroll
        for (int i = 0; i < BV; i++) {
            int idx = tid + i * THREADS;
            int n   = idx / (BK / 8);
            int kc  = (idx % (BK / 8)) * 8;
            uint4 v = __ldg(reinterpret_cast<const uint4*>(Bt + (size_t)(col0 + n) * K + kt + kc));
            *reinterpret_cast<uint4*>(&Bs[n][kc]) = v;
        }
        __syncthreads();

#pragma unroll
        for (int ks = 0; ks < BK; ks += 16) {
            uint32_t af[MI][4];
            uint32_t bf[NI][2];
#pragma unroll
            for (int i = 0; i < MI; i++) {
                int m0 = wm * WM + i * 16;
                af[i][0] = *reinterpret_cast<const uint32_t*>(&As[m0 + lq    ][ks + 2 * lr    ]);
                af[i][1] = *reinterpret_cast<const uint32_t*>(&As[m0 + lq + 8][ks + 2 * lr    ]);
                af[i][2] = *reinterpret_cast<const uint32_t*>(&As[m0 + lq    ][ks + 2 * lr + 8]);
                af[i][3] = *reinterpret_cast<const uint32_t*>(&As[m0 + lq + 8][ks + 2 * lr + 8]);
            }
#pragma unroll
            for (int j = 0; j < NI; j++) {
                int n0 = wn * WN + j * 8;
                bf[j][0] = *reinterpret_cast<const uint32_t*>(&Bs[n0 + lq][ks + 2 * lr    ]);
                bf[j][1] = *reinterpret_cast<const uint32_t*>(&Bs[n0 + lq][ks + 2 * lr + 8]);
            }
#pragma unroll
            for (int i = 0; i < MI; i++)
#pragma unroll
                for (int j = 0; j < NI; j++)
                    mma_f16(acc[i][j][0], acc[i][j][1], acc[i][j][2], acc[i][j][3],
                            af[i][0], af[i][1], af[i][2], af[i][3],
                            bf[j][0], bf[j][1]);
        }
        __syncthreads();
    }

#pragma unroll
    for (int i = 0; i < MI; i++) {
#pragma unroll
        for (int j = 0; j < NI; j++) {
            int row = row0 + wm * WM + i * 16 + lq;
            int col = col0 + wn * WN + j * 8 + 2 * lr;
            float2 v0 = make_float2(acc[i][j][0], acc[i][j][1]);
            float2 v1 = make_float2(acc[i][j][2], acc[i][j][3]);
            if (EPI) {
                float b0 = bias[col], b1 = bias[col + 1];
                v0.x = fmaxf(v0.x + b0, 0.f);
                v0.y = fmaxf(v0.y + b1, 0.f);
                v1.x = fmaxf(v1.x + b0, 0.f);
                v1.y = fmaxf(v1.y + b1, 0.f);
            }
            if (row < M)
                *reinterpret_cast<__half2*>(&C[(size_t)row * N + col]) =
                    __floats2half2_rn(v0.x, v0.y);
            if (row + 8 < M)
                *reinterpret_cast<__half2*>(&C[(size_t)(row + 8) * N + col]) =
                    __floats2half2_rn(v1.x, v1.y);
        }
    }
}

// GEMM1: g_hh = relu(g_a1h @ W1 + b1)   [50000x128]@[128x256]
__global__ void __launch_bounds__(256) gemm1_k(const float* __restrict__ b1) {
    gemm_f16_body<128, 128, 32, 2, 4, true>(g_a1h, g_w1h, b1, g_hh, N_NODESC, D1C, IN_C);
}

// GEMM2: g_y2h = g_hh @ W2   [50000x256]@[256x64]
__global__ void __launch_bounds__(256) gemm2_k() {
    gemm_f16_body<128, 64, 32, 4, 2, false>(g_hh, g_w2h, nullptr, g_y2h, N_NODESC, D2C, D1C);
}

// ---------------------------------------------------------------------------
// Launch (9 kernels)
// ---------------------------------------------------------------------------
extern "C" void kernel_launch(void* const* d_in, const int* in_sizes, int n_in,
                              void* d_out, int out_size) {
    const float* x    = (const float*)d_in[0];
    const int*   edge = (const int*)d_in[1];
    const float* W1   = (const float*)d_in[2];
    const float* b1   = (const float*)d_in[3];
    const float* W2   = (const float*)d_in[4];
    const float* b2   = (const float*)d_in[5];
    float*       out  = (float*)d_out;

    const int* ni = edge;          // edge[0] = node_idx
    const int* hi = edge + NNZC;   // edge[1] = hedge_idx

    // fused hist + conversions + barrier reset; then scan + scatter
    cvt_k<<<1024, 256>>>(x, W1, W2, ni, hi);
    scan_k<<<NBLK, 256>>>();
    build_k<<<(NNZC / 2 + 255) / 256, 256>>>(ni, hi);

    // Layer 1 aggregation at 128 channels (split hedge-side gather)
    n2h1_k<<<N_HEDGESC / 4, 256>>>();
    h2n1_k<<<(N_NODESC + 7) / 8, 256>>>();

    // h = relu(agg1 @ W1 + b1) ; y2 = h @ W2   (fp16 tensor cores)
    {
        dim3 g1(D1C / 128, (N_NODESC + 127) / 128);
        gemm1_k<<<g1, 256>>>(b1);
        dim3 g2(D2C / 64, (N_NODESC + 127) / 128);
        gemm2_k<<<g2, 256>>>();
    }

    // Layer 2 aggregation at 64 channels (split hedge-side gather) + epilogue
    n2h2_k<<<N_HEDGESC / 8, 256>>>();
    h2n2_k<<<(N_NODESC + 15) / 16, 256>>>(b2, out);
}